// round 1
// baseline (speedup 1.0000x reference)
#include <cuda_runtime.h>
#include <cstdint>
#include <cstddef>

// Problem constants (fixed by the reference)
#define RN 6
#define NN 50000
#define EE 200000
#define DD 768
#define HC 256      // H*C
#define OO 64

// ---------------------------------------------------------------------------
// Scratch: one big device-global array, carved into regions.
// Layout (floats):
//   XLR  : [N][512]  xl = cols 0..255, xr = cols 256..511     25,600,000
//   ea   : [E+N][4]  exp(logits)                               1,000,000
//   h1   : [N][64]   layer-1 output                            3,200,000
//   -- accumulators (zeroed each relation, contiguous) --
//   denom: [N][4]                                                200,000
//   gat  : [N][256]  GAT aggregate, then in-place h=relu(+b)  12,800,000
//   agg1 : [N][256]                                           12,800,000
//   agg2 : [N][64]                                             3,200,000
// total: 58,800,000 floats = 235.2 MB
// ---------------------------------------------------------------------------
__device__ float g_scratch[58800000];

#define OFF_XLR   0
#define OFF_EA    25600000
#define OFF_H1    26600000
#define OFF_DENOM 29800000
#define OFF_GAT   30000000
#define OFF_AGG1  42800000
#define OFF_AGG2  55600000
#define ZERO_LEN  29000000   // denom..agg2 contiguous

// ---------------------------------------------------------------------------
// Vector reductions (sm_90+): quarter the atomic issue count vs scalar REDG
// ---------------------------------------------------------------------------
__device__ __forceinline__ void red_add_v4(float* p, float a, float b, float c, float d) {
    asm volatile("red.global.add.v4.f32 [%0], {%1,%2,%3,%4};"
                 :: "l"(p), "f"(a), "f"(b), "f"(c), "f"(d) : "memory");
}
__device__ __forceinline__ void red_add_v2(float* p, float a, float b) {
    asm volatile("red.global.add.v2.f32 [%0], {%1,%2};"
                 :: "l"(p), "f"(a), "f"(b) : "memory");
}

// ---------------------------------------------------------------------------
// fill zero (float4 grid-stride)
// ---------------------------------------------------------------------------
__global__ void fill_zero_kernel(float4* p, int n4) {
    int i = blockIdx.x * blockDim.x + threadIdx.x;
    int stride = gridDim.x * blockDim.x;
    float4 z = make_float4(0.f, 0.f, 0.f, 0.f);
    for (; i < n4; i += stride) p[i] = z;
}

// ---------------------------------------------------------------------------
// Big GEMM: XLR[n][0:256] = x @ Wl,  XLR[n][256:512] = x @ Wr
// M=50000, K=768, Ncols=512. 128x128 tile, BK=16, 256 thr, 8x8 micro-tile.
// grid.x = 4 column tiles (tiles 0,1 -> Wl ; 2,3 -> Wr), grid.y = row tiles.
// ---------------------------------------------------------------------------
__global__ void __launch_bounds__(256)
gemm_xlr_kernel(const float* __restrict__ X, const float* __restrict__ Wl,
                const float* __restrict__ Wr, float* __restrict__ C, int M) {
    const int K = DD;
    int colTile = blockIdx.x;
    const float* B = (colTile < 2) ? Wl : Wr;
    int bcol0 = (colTile & 1) * 128;
    int brow0 = blockIdx.y * 128;

    __shared__ float As[16][132];
    __shared__ float Bs[16][128];

    int tid = threadIdx.x;
    int tx = tid & 15, ty = tid >> 4;
    float acc[8][8];
#pragma unroll
    for (int i = 0; i < 8; i++)
#pragma unroll
        for (int j = 0; j < 8; j++) acc[i][j] = 0.f;

    for (int k0 = 0; k0 < K; k0 += 16) {
#pragma unroll
        for (int l = 0; l < 2; l++) {
            int lin = tid + l * 256;
            int ar = lin >> 2, ak = (lin & 3) * 4;
            float4 v = make_float4(0.f, 0.f, 0.f, 0.f);
            int gr = brow0 + ar;
            if (gr < M) v = *(const float4*)(X + (size_t)gr * DD + k0 + ak);
            As[ak + 0][ar] = v.x; As[ak + 1][ar] = v.y;
            As[ak + 2][ar] = v.z; As[ak + 3][ar] = v.w;

            int br = lin >> 5, bc = (lin & 31) * 4;
            float4 w = *(const float4*)(B + (size_t)(k0 + br) * HC + bcol0 + bc);
            *(float4*)&Bs[br][bc] = w;
        }
        __syncthreads();
#pragma unroll
        for (int kk = 0; kk < 16; kk++) {
            float a[8], b[8];
#pragma unroll
            for (int i = 0; i < 8; i++) a[i] = As[kk][ty * 8 + i];
#pragma unroll
            for (int j = 0; j < 8; j++) b[j] = Bs[kk][tx * 8 + j];
#pragma unroll
            for (int i = 0; i < 8; i++)
#pragma unroll
                for (int j = 0; j < 8; j++) acc[i][j] += a[i] * b[j];
        }
        __syncthreads();
    }

    int ccol0 = colTile * 128 + tx * 8;
#pragma unroll
    for (int i = 0; i < 8; i++) {
        int gr = brow0 + ty * 8 + i;
        if (gr < M) {
            float* cp = C + (size_t)gr * 512 + ccol0;
            *(float4*)cp       = make_float4(acc[i][0], acc[i][1], acc[i][2], acc[i][3]);
            *(float4*)(cp + 4) = make_float4(acc[i][4], acc[i][5], acc[i][6], acc[i][7]);
        }
    }
}

// ---------------------------------------------------------------------------
// GAT pass A': per edge, logits = einsum(leakyrelu(xl[s]+xr[t]), att),
// a = exp(logits) (max-free softmax; logits are small), denom[t] += a.
// One warp per edge; lane handles 8 contiguous channels (head = lane/8).
// ---------------------------------------------------------------------------
__global__ void gat_logits_kernel(const float* __restrict__ XLR,
                                  const int* __restrict__ src, const int* __restrict__ tgt,
                                  const float* __restrict__ att,
                                  float* __restrict__ ea, float* __restrict__ denom) {
    int warp = (blockIdx.x * blockDim.x + threadIdx.x) >> 5;
    int lane = threadIdx.x & 31;
    int total = EE + NN;
    if (warp >= total) return;
    int s, t;
    if (warp < EE) { s = src[warp]; t = tgt[warp]; }
    else           { s = t = warp - EE; }

    const float* xl = XLR + (size_t)s * 512;
    const float* xr = XLR + (size_t)t * 512 + 256;
    int base = lane * 8;
    float4 l0 = *(const float4*)(xl + base), l1 = *(const float4*)(xl + base + 4);
    float4 r0 = *(const float4*)(xr + base), r1 = *(const float4*)(xr + base + 4);
    float4 a0 = *(const float4*)(att + base), a1 = *(const float4*)(att + base + 4);

#define LRELU(v) ((v) > 0.f ? (v) : 0.2f * (v))
    float sum = LRELU(l0.x + r0.x) * a0.x + LRELU(l0.y + r0.y) * a0.y
              + LRELU(l0.z + r0.z) * a0.z + LRELU(l0.w + r0.w) * a0.w
              + LRELU(l1.x + r1.x) * a1.x + LRELU(l1.y + r1.y) * a1.y
              + LRELU(l1.z + r1.z) * a1.z + LRELU(l1.w + r1.w) * a1.w;
#undef LRELU
    // reduce within 8-lane head groups
    sum += __shfl_xor_sync(0xffffffffu, sum, 1);
    sum += __shfl_xor_sync(0xffffffffu, sum, 2);
    sum += __shfl_xor_sync(0xffffffffu, sum, 4);

    if ((lane & 7) == 0) {
        int h = lane >> 3;
        float e = expf(sum);
        ea[(size_t)warp * 4 + h] = e;
        atomicAdd(denom + (size_t)t * 4 + h, e);
    }
}

// ---------------------------------------------------------------------------
// GAT pass B': alpha = a/(denom[t]+1e-16); gat[t] += xl[s]*alpha
// ---------------------------------------------------------------------------
__global__ void gat_scatter_kernel(const float* __restrict__ XLR,
                                   const int* __restrict__ src, const int* __restrict__ tgt,
                                   const float* __restrict__ ea, const float* __restrict__ denom,
                                   float* __restrict__ gat) {
    int warp = (blockIdx.x * blockDim.x + threadIdx.x) >> 5;
    int lane = threadIdx.x & 31;
    int total = EE + NN;
    if (warp >= total) return;
    int s, t;
    if (warp < EE) { s = src[warp]; t = tgt[warp]; }
    else           { s = t = warp - EE; }

    int h = lane >> 3;
    float aE = ea[(size_t)warp * 4 + h];
    float dn = denom[(size_t)t * 4 + h];
    float alpha = aE / (dn + 1e-16f);

    int base = lane * 8;
    const float* xl = XLR + (size_t)s * 512 + base;
    float4 v0 = *(const float4*)xl, v1 = *(const float4*)(xl + 4);
    float* dst = gat + (size_t)t * 256 + base;
    red_add_v4(dst,     v0.x * alpha, v0.y * alpha, v0.z * alpha, v0.w * alpha);
    red_add_v4(dst + 4, v1.x * alpha, v1.y * alpha, v1.z * alpha, v1.w * alpha);
}

// ---------------------------------------------------------------------------
// In-place h = relu(gat + b_gat)  (b index = channel % 256)
// ---------------------------------------------------------------------------
__global__ void bias_relu_kernel(float4* __restrict__ g, const float4* __restrict__ b, int n4) {
    int i = blockIdx.x * blockDim.x + threadIdx.x;
    if (i >= n4) return;
    float4 v = g[i];
    float4 bb = b[i & 63];   // 256 floats = 64 float4 per row
    v.x = fmaxf(v.x + bb.x, 0.f);
    v.y = fmaxf(v.y + bb.y, 0.f);
    v.z = fmaxf(v.z + bb.z, 0.f);
    v.w = fmaxf(v.w + bb.w, 0.f);
    g[i] = v;
}

// ---------------------------------------------------------------------------
// GraphConv aggregation: agg[t][:] += h[s][:], width 256 (warp/edge, 8 f/lane)
// ---------------------------------------------------------------------------
__global__ void gather_add256_kernel(const float* __restrict__ h,
                                     const int* __restrict__ src, const int* __restrict__ tgt,
                                     float* __restrict__ agg) {
    int warp = (blockIdx.x * blockDim.x + threadIdx.x) >> 5;
    int lane = threadIdx.x & 31;
    if (warp >= EE) return;
    int s = src[warp], t = tgt[warp];
    int base = lane * 8;
    const float* hp = h + (size_t)s * 256 + base;
    float4 v0 = *(const float4*)hp, v1 = *(const float4*)(hp + 4);
    float* dst = agg + (size_t)t * 256 + base;
    red_add_v4(dst,     v0.x, v0.y, v0.z, v0.w);
    red_add_v4(dst + 4, v1.x, v1.y, v1.z, v1.w);
}

// width 64 (warp/edge, 2 floats/lane)
__global__ void gather_add64_kernel(const float* __restrict__ h,
                                    const int* __restrict__ src, const int* __restrict__ tgt,
                                    float* __restrict__ agg) {
    int warp = (blockIdx.x * blockDim.x + threadIdx.x) >> 5;
    int lane = threadIdx.x & 31;
    if (warp >= EE) return;
    int s = src[warp], t = tgt[warp];
    float2 v = *(const float2*)(h + (size_t)s * 64 + lane * 2);
    red_add_v2(agg + (size_t)t * 64 + lane * 2, v.x, v.y);
}

// ---------------------------------------------------------------------------
// GraphConv GEMM: C[m][j] = bias[j] + A1[m]@B1 + A2[m]@B2, optional relu.
// A1,A2: [M][K1] row-major; B1,B2: [K1][64] row-major; K1 in {256,64}.
// 64x64 tile, BK=32, 256 threads, 4x4 micro-tile.
// ---------------------------------------------------------------------------
__global__ void __launch_bounds__(256)
graphconv_gemm_kernel(const float* __restrict__ A1, const float* __restrict__ A2,
                      const float* __restrict__ B1, const float* __restrict__ B2,
                      const float* __restrict__ bias, float* __restrict__ C,
                      int ldc, int M, int K1, int relu_out) {
    __shared__ float As[32][68];
    __shared__ float Bs[32][64];
    int m0 = blockIdx.x * 64;
    int tid = threadIdx.x;
    int tx = tid & 15, ty = tid >> 4;
    float acc[4][4];
#pragma unroll
    for (int i = 0; i < 4; i++)
#pragma unroll
        for (int j = 0; j < 4; j++) acc[i][j] = 0.f;

    for (int k0 = 0; k0 < 2 * K1; k0 += 32) {
        const float* A = (k0 < K1) ? A1 : A2;
        const float* B = (k0 < K1) ? B1 : B2;
        int kk = (k0 < K1) ? k0 : (k0 - K1);
#pragma unroll
        for (int l = 0; l < 2; l++) {
            int lin = tid + l * 256;
            int row = lin >> 3, kc = (lin & 7) * 4;
            float4 v = make_float4(0.f, 0.f, 0.f, 0.f);
            int gm = m0 + row;
            if (gm < M) v = *(const float4*)(A + (size_t)gm * K1 + kk + kc);
            As[kc + 0][row] = v.x; As[kc + 1][row] = v.y;
            As[kc + 2][row] = v.z; As[kc + 3][row] = v.w;

            int br = lin >> 4, bc = (lin & 15) * 4;
            *(float4*)&Bs[br][bc] = *(const float4*)(B + (size_t)(kk + br) * 64 + bc);
        }
        __syncthreads();
#pragma unroll
        for (int k = 0; k < 32; k++) {
            float a[4], b[4];
#pragma unroll
            for (int i = 0; i < 4; i++) a[i] = As[k][ty * 4 + i];
#pragma unroll
            for (int j = 0; j < 4; j++) b[j] = Bs[k][tx * 4 + j];
#pragma unroll
            for (int i = 0; i < 4; i++)
#pragma unroll
                for (int j = 0; j < 4; j++) acc[i][j] += a[i] * b[j];
        }
        __syncthreads();
    }

    float bj[4];
#pragma unroll
    for (int j = 0; j < 4; j++) bj[j] = bias[tx * 4 + j];
#pragma unroll
    for (int i = 0; i < 4; i++) {
        int gm = m0 + ty * 4 + i;
        if (gm < M) {
            float4 o;
            o.x = acc[i][0] + bj[0];
            o.y = acc[i][1] + bj[1];
            o.z = acc[i][2] + bj[2];
            o.w = acc[i][3] + bj[3];
            if (relu_out) {
                o.x = fmaxf(o.x, 0.f); o.y = fmaxf(o.y, 0.f);
                o.z = fmaxf(o.z, 0.f); o.w = fmaxf(o.w, 0.f);
            }
            *(float4*)(C + (size_t)gm * ldc + tx * 4) = o;
        }
    }
}

// ---------------------------------------------------------------------------
// launch
// ---------------------------------------------------------------------------
extern "C" void kernel_launch(void* const* d_in, const int* in_sizes, int n_in,
                              void* d_out, int out_size) {
    const float* x      = (const float*)d_in[0];
    const int*   ei     = (const int*)  d_in[1];   // [R,2,E]
    const float* Wl     = (const float*)d_in[2];   // [R,768,256]
    const float* Wr     = (const float*)d_in[3];
    const float* att    = (const float*)d_in[4];   // [R,4,64]
    const float* bg     = (const float*)d_in[5];   // [R,256]
    const float* Wrel1  = (const float*)d_in[6];   // [R,256,64]
    const float* Wroot1 = (const float*)d_in[7];
    const float* b1     = (const float*)d_in[8];   // [R,64]
    const float* Wrel2  = (const float*)d_in[9];   // [R,64,64]
    const float* Wroot2 = (const float*)d_in[10];
    const float* b2     = (const float*)d_in[11];  // [R,64]
    float* out = (float*)d_out;                    // [N,R,64]

    float* scratch = nullptr;
    cudaGetSymbolAddress((void**)&scratch, g_scratch);
    float* XLR   = scratch + OFF_XLR;
    float* ea    = scratch + OFF_EA;
    float* h1    = scratch + OFF_H1;
    float* denom = scratch + OFF_DENOM;
    float* gat   = scratch + OFF_GAT;
    float* agg1  = scratch + OFF_AGG1;
    float* agg2  = scratch + OFF_AGG2;

    const int M = NN;
    int edgeBlocks     = (EE + NN + 7) / 8;  // warp per edge, 8 warps/block
    int gatherBlocks   = (EE + 7) / 8;

    for (int r = 0; r < RN; r++) {
        const int* src = ei + (size_t)r * 2 * EE;
        const int* tgt = src + EE;

        // zero accumulators (denom..agg2 contiguous)
        fill_zero_kernel<<<4096, 256>>>((float4*)denom, ZERO_LEN / 4);

        // xl | xr = x @ [Wl | Wr]
        gemm_xlr_kernel<<<dim3(4, (M + 127) / 128), 256>>>(
            x, Wl + (size_t)r * DD * HC, Wr + (size_t)r * DD * HC, XLR, M);

        // GATv2 edge phase
        gat_logits_kernel<<<edgeBlocks, 256>>>(XLR, src, tgt, att + (size_t)r * HC, ea, denom);
        gat_scatter_kernel<<<edgeBlocks, 256>>>(XLR, src, tgt, ea, denom, gat);

        // h = relu(gat + b_gat), in place
        bias_relu_kernel<<<(M * 64 + 255) / 256, 256>>>(
            (float4*)gat, (const float4*)(bg + (size_t)r * HC), M * 64);

        // GraphConv 1
        gather_add256_kernel<<<gatherBlocks, 256>>>(gat, src, tgt, agg1);
        graphconv_gemm_kernel<<<(M + 63) / 64, 256>>>(
            agg1, gat,
            Wrel1 + (size_t)r * HC * OO, Wroot1 + (size_t)r * HC * OO,
            b1 + (size_t)r * OO, h1, OO, M, HC, 1);

        // GraphConv 2 -> output slice [:, r, :]
        gather_add64_kernel<<<gatherBlocks, 256>>>(h1, src, tgt, agg2);
        graphconv_gemm_kernel<<<(M + 63) / 64, 256>>>(
            agg2, h1,
            Wrel2 + (size_t)r * OO * OO, Wroot2 + (size_t)r * OO * OO,
            b2 + (size_t)r * OO, out + (size_t)r * OO, RN * OO, M, OO, 0);
    }
}

// round 3
// speedup vs baseline: 2.3087x; 2.3087x over previous
#include <cuda_runtime.h>
#include <cstdint>
#include <cstddef>

// Problem constants (fixed by the reference)
#define RN 6
#define NN 50000
#define EE 200000
#define DD 768
#define HC 256      // H*C
#define OO 64

// ---------------------------------------------------------------------------
// Scratch layout (floats)
//   XLR  : [N][512]   xl|xr                                    25,600,000
//   ea   : [E+N][4]   exp(logits)                               1,000,000
//   h1   : [N][64]                                              3,200,000
//   p1   : [N][64]    h@W_rel1                                  3,200,000
//   p2   : [N][64]    h1@W_rel2                                 3,200,000
//   denom: [N][4]     (zeroed per relation)                       200,000
//   gat  : [N][256]   (zeroed per relation)                    12,800,000
//   XR   : [N][768]   tf32-rounded x                           38,400,000
//   WT   : [R][512][768] tf32-rounded [Wl|Wr]^T                 2,359,296
// ---------------------------------------------------------------------------
__device__ float g_scratch[89959296];

#define OFF_XLR   0u
#define OFF_EA    25600000u
#define OFF_H1    26600000u
#define OFF_P1    29800000u
#define OFF_P2    33000000u
#define OFF_DENOM 36200000u
#define OFF_GAT   36400000u
#define OFF_XR    49200000u
#define OFF_WT    87600000u
#define ZERO_LEN  13000000u   // denom + gat contiguous

// ===========================================================================
// PTX helpers (all plain-sm_103-legal: cp.async, ldmatrix, mma.sync, red)
// ===========================================================================
__device__ __forceinline__ uint32_t smem_u32(const void* p) {
    uint32_t a;
    asm("{ .reg .u64 t; cvta.to.shared.u64 t, %1; cvt.u32.u64 %0, t; }"
        : "=r"(a) : "l"(p));
    return a;
}
__device__ __forceinline__ void cp16(uint32_t dst, const void* src, uint32_t sz) {
    asm volatile("cp.async.cg.shared.global [%0], [%1], 16, %2;"
                 :: "r"(dst), "l"(src), "r"(sz) : "memory");
}
__device__ __forceinline__ void cp_commit() {
    asm volatile("cp.async.commit_group;" ::: "memory");
}
__device__ __forceinline__ void cp_wait1() {
    asm volatile("cp.async.wait_group 1;" ::: "memory");
}
#define LDSM4(r0, r1, r2, r3, addr) \
    asm volatile("ldmatrix.sync.aligned.m8n8.x4.shared.b16 {%0,%1,%2,%3}, [%4];" \
                 : "=r"(r0), "=r"(r1), "=r"(r2), "=r"(r3) : "r"(addr))

#define MMA_TF32(d, a, b0, b1) \
    asm volatile("mma.sync.aligned.m16n8k8.row.col.f32.tf32.tf32.f32 " \
                 "{%0,%1,%2,%3}, {%4,%5,%6,%7}, {%8,%9}, {%0,%1,%2,%3};" \
                 : "+f"((d)[0]), "+f"((d)[1]), "+f"((d)[2]), "+f"((d)[3]) \
                 : "r"((a)[0]), "r"((a)[1]), "r"((a)[2]), "r"((a)[3]), \
                   "r"(b0), "r"(b1))

// Vector reductions
__device__ __forceinline__ void red_add_v4(float* p, float a, float b, float c, float d) {
    asm volatile("red.global.add.v4.f32 [%0], {%1,%2,%3,%4};"
                 :: "l"(p), "f"(a), "f"(b), "f"(c), "f"(d) : "memory");
}
__device__ __forceinline__ void red_add_v2(float* p, float a, float b) {
    asm volatile("red.global.add.v2.f32 [%0], {%1,%2};"
                 :: "l"(p), "f"(a), "f"(b) : "memory");
}

// ===========================================================================
// Preprocessing: tf32 rounding + weight transpose
// ===========================================================================
__device__ __forceinline__ float rna_tf32(float v) {
    uint32_t o;
    asm("cvt.rna.tf32.f32 %0, %1;" : "=r"(o) : "f"(v));
    return __uint_as_float(o);
}

__global__ void round_tf32_kernel(const float4* __restrict__ in, float4* __restrict__ out, int n4) {
    int i = blockIdx.x * blockDim.x + threadIdx.x;
    int stride = gridDim.x * blockDim.x;
    for (; i < n4; i += stride) {
        float4 v = in[i];
        v.x = rna_tf32(v.x); v.y = rna_tf32(v.y);
        v.z = rna_tf32(v.z); v.w = rna_tf32(v.w);
        out[i] = v;
    }
}

// WT[r][n][k] = rna(Wl[r][k][n]) for n<256, rna(Wr[r][k][n-256]) otherwise
__global__ void transpose_w_kernel(const float* __restrict__ Wl, const float* __restrict__ Wr,
                                   float* __restrict__ WT) {
    __shared__ float tile[32][33];
    int r = blockIdx.z;
    int k0 = blockIdx.x * 32;   // 24 blocks
    int n0 = blockIdx.y * 32;   // 16 blocks
    const float* W = (n0 < 256) ? Wl : Wr;
    int nc0 = (n0 < 256) ? n0 : (n0 - 256);
    int tx = threadIdx.x, ty = threadIdx.y;  // 32 x 8
#pragma unroll
    for (int i = 0; i < 32; i += 8) {
        float v = W[((size_t)r * DD + k0 + ty + i) * HC + nc0 + tx];
        tile[ty + i][tx] = rna_tf32(v);
    }
    __syncthreads();
#pragma unroll
    for (int i = 0; i < 32; i += 8) {
        WT[((size_t)r * 512 + n0 + ty + i) * DD + k0 + tx] = tile[tx][ty + i];
    }
}

// ===========================================================================
// fill zero
// ===========================================================================
__global__ void fill_zero_kernel(float4* p, int n4) {
    int i = blockIdx.x * blockDim.x + threadIdx.x;
    int stride = gridDim.x * blockDim.x;
    float4 z = make_float4(0.f, 0.f, 0.f, 0.f);
    for (; i < n4; i += stride) p[i] = z;
}

// ===========================================================================
// tf32 mma.sync GEMM: C[M][512] tile = A[M][768] @ B[512][768]^T
// A row-major, B K-major ([n][k]). BM=128 BN=128 BK=32, 3-stage cp.async.
// 256 threads = 8 warps (2 m x 4 n), warp tile 64x32, mma m16n8k8.
// ===========================================================================
#define BM 128
#define BN 128
#define BK 32
#define GSTG 3
#define KIT (DD / BK)               // 24
#define TILE_BYTES (BM * BK * 4)    // 16384
#define SMEM_GEMM (GSTG * 2 * TILE_BYTES + 1024)

__global__ void __launch_bounds__(256, 1)
gemm_xlr_mma_kernel(const float* __restrict__ A, const float* __restrict__ B,
                    float* __restrict__ C, int M) {
    extern __shared__ char sm_raw[];
    uint32_t smbase = (smem_u32(sm_raw) + 1023u) & ~1023u;
    uint32_t sA = smbase;                      // 3 x 16KB
    uint32_t sB = smbase + GSTG * TILE_BYTES;  // 3 x 16KB

    int tid = threadIdx.x;
    int lane = tid & 31, wid = tid >> 5;
    int wm = wid & 1, wn = wid >> 1;
    int M0 = blockIdx.y * BM, N0 = blockIdx.x * BN;

    // --- cp.async mapping: 1024 16B chunks per tile, 4 per thread ---
    uint32_t dstOff[4];
    const float* srcA[4]; uint32_t szA[4];
    const float* srcB[4];
#pragma unroll
    for (int i = 0; i < 4; i++) {
        int lin = tid + i * 256;
        int row = lin >> 3, ch = lin & 7;
        dstOff[i] = row * 128 + ((ch * 16) ^ ((row & 7) * 16));
        int ga = M0 + row;
        szA[i] = (ga < M) ? 16u : 0u;
        srcA[i] = A + (size_t)(ga < M ? ga : 0) * DD + ch * 4;
        srcB[i] = B + (size_t)(N0 + row) * DD + ch * 4;
    }

    // --- ldmatrix address bases (swizzle folded in; XOR ks*32 at use) ---
    uint32_t aOff[4], bOff[2];
#pragma unroll
    for (int mt = 0; mt < 4; mt++) {
        int rowA = wm * 64 + mt * 16 + (lane & 7) + ((lane >> 3) & 1) * 8;
        uint32_t q = (uint32_t)(((lane >> 4) * 16) ^ ((rowA & 7) * 16));
        aOff[mt] = (uint32_t)rowA * 128 + q;
    }
#pragma unroll
    for (int bp = 0; bp < 2; bp++) {
        int rowB = wn * 32 + bp * 16 + (lane & 7) + ((lane >> 4) & 1) * 8;
        uint32_t q = (uint32_t)((((lane >> 3) & 1) * 16) ^ ((rowB & 7) * 16));
        bOff[bp] = (uint32_t)rowB * 128 + q;
    }

    float acc[4][4][4];
#pragma unroll
    for (int mt = 0; mt < 4; mt++)
#pragma unroll
        for (int nt = 0; nt < 4; nt++)
#pragma unroll
            for (int j = 0; j < 4; j++) acc[mt][nt][j] = 0.f;

    // --- prologue: stages 0 and 1 ---
#pragma unroll
    for (int s = 0; s < 2; s++) {
#pragma unroll
        for (int i = 0; i < 4; i++) {
            cp16(sA + s * TILE_BYTES + dstOff[i], srcA[i] + s * BK, szA[i]);
            cp16(sB + s * TILE_BYTES + dstOff[i], srcB[i] + s * BK, 16u);
        }
        cp_commit();
    }

    for (int it = 0; it < KIT; it++) {
        cp_wait1();
        __syncthreads();

        int nx = it + 2;
        if (nx < KIT) {
            int s2 = nx % GSTG;
#pragma unroll
            for (int i = 0; i < 4; i++) {
                cp16(sA + s2 * TILE_BYTES + dstOff[i], srcA[i] + nx * BK, szA[i]);
                cp16(sB + s2 * TILE_BYTES + dstOff[i], srcB[i] + nx * BK, 16u);
            }
        }
        cp_commit();

        int s = it % GSTG;
        uint32_t baseA = sA + s * TILE_BYTES;
        uint32_t baseB = sB + s * TILE_BYTES;
#pragma unroll
        for (int ks = 0; ks < 4; ks++) {
            uint32_t afr[4][4];
            uint32_t bfr[4][2];
#pragma unroll
            for (int mt = 0; mt < 4; mt++)
                LDSM4(afr[mt][0], afr[mt][1], afr[mt][2], afr[mt][3],
                      baseA + (aOff[mt] ^ (uint32_t)(ks * 32)));
#pragma unroll
            for (int bp = 0; bp < 2; bp++) {
                uint32_t r0, r1, r2, r3;
                LDSM4(r0, r1, r2, r3, baseB + (bOff[bp] ^ (uint32_t)(ks * 32)));
                bfr[2 * bp][0] = r0;     bfr[2 * bp][1] = r1;
                bfr[2 * bp + 1][0] = r2; bfr[2 * bp + 1][1] = r3;
            }
#pragma unroll
            for (int mt = 0; mt < 4; mt++)
#pragma unroll
                for (int nt = 0; nt < 4; nt++)
                    MMA_TF32(acc[mt][nt], afr[mt], bfr[nt][0], bfr[nt][1]);
        }
    }

    // --- epilogue: c0 (r, c) c1 (r, c+1) c2 (r+8, c) c3 (r+8, c+1) ---
    int r = lane >> 2, c = (lane & 3) * 2;
#pragma unroll
    for (int mt = 0; mt < 4; mt++) {
        int grow = M0 + wm * 64 + mt * 16 + r;
#pragma unroll
        for (int nt = 0; nt < 4; nt++) {
            int gcol = N0 + wn * 32 + nt * 8 + c;
            if (grow < M)
                *(float2*)(C + (size_t)grow * 512 + gcol) =
                    make_float2(acc[mt][nt][0], acc[mt][nt][1]);
            if (grow + 8 < M)
                *(float2*)(C + (size_t)(grow + 8) * 512 + gcol) =
                    make_float2(acc[mt][nt][2], acc[mt][nt][3]);
        }
    }
}

// ===========================================================================
// GATv2 edge kernels (validated in R1)
// ===========================================================================
__global__ void gat_logits_kernel(const float* __restrict__ XLR,
                                  const int* __restrict__ src, const int* __restrict__ tgt,
                                  const float* __restrict__ att,
                                  float* __restrict__ ea, float* __restrict__ denom) {
    int warp = (blockIdx.x * blockDim.x + threadIdx.x) >> 5;
    int lane = threadIdx.x & 31;
    int total = EE + NN;
    if (warp >= total) return;
    int s, t;
    if (warp < EE) { s = src[warp]; t = tgt[warp]; }
    else           { s = t = warp - EE; }

    const float* xl = XLR + (size_t)s * 512;
    const float* xr = XLR + (size_t)t * 512 + 256;
    int base = lane * 8;
    float4 l0 = *(const float4*)(xl + base), l1 = *(const float4*)(xl + base + 4);
    float4 r0 = *(const float4*)(xr + base), r1 = *(const float4*)(xr + base + 4);
    float4 a0 = *(const float4*)(att + base), a1 = *(const float4*)(att + base + 4);

#define LRELU(v) ((v) > 0.f ? (v) : 0.2f * (v))
    float sum = LRELU(l0.x + r0.x) * a0.x + LRELU(l0.y + r0.y) * a0.y
              + LRELU(l0.z + r0.z) * a0.z + LRELU(l0.w + r0.w) * a0.w
              + LRELU(l1.x + r1.x) * a1.x + LRELU(l1.y + r1.y) * a1.y
              + LRELU(l1.z + r1.z) * a1.z + LRELU(l1.w + r1.w) * a1.w;
#undef LRELU
    sum += __shfl_xor_sync(0xffffffffu, sum, 1);
    sum += __shfl_xor_sync(0xffffffffu, sum, 2);
    sum += __shfl_xor_sync(0xffffffffu, sum, 4);

    if ((lane & 7) == 0) {
        int h = lane >> 3;
        float e = expf(sum);
        ea[(size_t)warp * 4 + h] = e;
        atomicAdd(denom + (size_t)t * 4 + h, e);
    }
}

__global__ void gat_scatter_kernel(const float* __restrict__ XLR,
                                   const int* __restrict__ src, const int* __restrict__ tgt,
                                   const float* __restrict__ ea, const float* __restrict__ denom,
                                   float* __restrict__ gat) {
    int warp = (blockIdx.x * blockDim.x + threadIdx.x) >> 5;
    int lane = threadIdx.x & 31;
    int total = EE + NN;
    if (warp >= total) return;
    int s, t;
    if (warp < EE) { s = src[warp]; t = tgt[warp]; }
    else           { s = t = warp - EE; }

    int h = lane >> 3;
    float aE = ea[(size_t)warp * 4 + h];
    float dn = denom[(size_t)t * 4 + h];
    float alpha = aE / (dn + 1e-16f);

    int base = lane * 8;
    const float* xl = XLR + (size_t)s * 512 + base;
    float4 v0 = *(const float4*)xl, v1 = *(const float4*)(xl + 4);
    float* dst = gat + (size_t)t * 256 + base;
    red_add_v4(dst,     v0.x * alpha, v0.y * alpha, v0.z * alpha, v0.w * alpha);
    red_add_v4(dst + 4, v1.x * alpha, v1.y * alpha, v1.z * alpha, v1.w * alpha);
}

__global__ void bias_relu_kernel(float4* __restrict__ g, const float4* __restrict__ b, int n4) {
    int i = blockIdx.x * blockDim.x + threadIdx.x;
    if (i >= n4) return;
    float4 v = g[i];
    float4 bb = b[i & 63];
    v.x = fmaxf(v.x + bb.x, 0.f);
    v.y = fmaxf(v.y + bb.y, 0.f);
    v.z = fmaxf(v.z + bb.z, 0.f);
    v.w = fmaxf(v.w + bb.w, 0.f);
    g[i] = v;
}

__global__ void relu64_kernel(float4* __restrict__ p, int n4) {
    int i = blockIdx.x * blockDim.x + threadIdx.x;
    if (i >= n4) return;
    float4 v = p[i];
    v.x = fmaxf(v.x, 0.f); v.y = fmaxf(v.y, 0.f);
    v.z = fmaxf(v.z, 0.f); v.w = fmaxf(v.w, 0.f);
    p[i] = v;
}

// scatter: dst[t][0:64] += p[s][0:64], dst row stride ldd
__global__ void scatter_add64_kernel(const float* __restrict__ p,
                                     const int* __restrict__ src, const int* __restrict__ tgt,
                                     float* __restrict__ dst, int ldd) {
    int warp = (blockIdx.x * blockDim.x + threadIdx.x) >> 5;
    int lane = threadIdx.x & 31;
    if (warp >= EE) return;
    int s = src[warp], t = tgt[warp];
    float2 v = *(const float2*)(p + (size_t)s * 64 + lane * 2);
    red_add_v2(dst + (size_t)t * ldd + lane * 2, v.x, v.y);
}

// ===========================================================================
// Dual small GEMM: C1 = A@B1 (no bias, ldc 64); C2 = A@B2 + bias (ldc param)
// A: [M][K] row-major, B: [K][64], K in {256, 64}.
// ===========================================================================
__global__ void __launch_bounds__(256)
gemm64_dual_kernel(const float* __restrict__ A,
                   const float* __restrict__ B1, const float* __restrict__ B2,
                   const float* __restrict__ bias,
                   float* __restrict__ C1, float* __restrict__ C2,
                   int ldc2, int M, int K) {
    __shared__ float As[32][68];
    __shared__ float B1s[32][64];
    __shared__ float B2s[32][64];
    int m0 = blockIdx.x * 64;
    int tid = threadIdx.x;
    int tx = tid & 15, ty = tid >> 4;
    float acc1[4][4], acc2[4][4];
#pragma unroll
    for (int i = 0; i < 4; i++)
#pragma unroll
        for (int j = 0; j < 4; j++) { acc1[i][j] = 0.f; acc2[i][j] = 0.f; }

    for (int k0 = 0; k0 < K; k0 += 32) {
#pragma unroll
        for (int l = 0; l < 2; l++) {
            int lin = tid + l * 256;
            int row = lin >> 3, kc = (lin & 7) * 4;
            float4 v = make_float4(0.f, 0.f, 0.f, 0.f);
            int gm = m0 + row;
            if (gm < M) v = *(const float4*)(A + (size_t)gm * K + k0 + kc);
            As[kc + 0][row] = v.x; As[kc + 1][row] = v.y;
            As[kc + 2][row] = v.z; As[kc + 3][row] = v.w;

            int br = lin >> 4, bc = (lin & 15) * 4;
            *(float4*)&B1s[br][bc] = *(const float4*)(B1 + (size_t)(k0 + br) * 64 + bc);
            *(float4*)&B2s[br][bc] = *(const float4*)(B2 + (size_t)(k0 + br) * 64 + bc);
        }
        __syncthreads();
#pragma unroll
        for (int k = 0; k < 32; k++) {
            float a[4], b1v[4], b2v[4];
#pragma unroll
            for (int i = 0; i < 4; i++) a[i] = As[k][ty * 4 + i];
#pragma unroll
            for (int j = 0; j < 4; j++) { b1v[j] = B1s[k][tx * 4 + j]; b2v[j] = B2s[k][tx * 4 + j]; }
#pragma unroll
            for (int i = 0; i < 4; i++)
#pragma unroll
                for (int j = 0; j < 4; j++) {
                    acc1[i][j] += a[i] * b1v[j];
                    acc2[i][j] += a[i] * b2v[j];
                }
        }
        __syncthreads();
    }

    float bj[4];
#pragma unroll
    for (int j = 0; j < 4; j++) bj[j] = bias[tx * 4 + j];
#pragma unroll
    for (int i = 0; i < 4; i++) {
        int gm = m0 + ty * 4 + i;
        if (gm < M) {
            *(float4*)(C1 + (size_t)gm * 64 + tx * 4) =
                make_float4(acc1[i][0], acc1[i][1], acc1[i][2], acc1[i][3]);
            *(float4*)(C2 + (size_t)gm * ldc2 + tx * 4) =
                make_float4(acc2[i][0] + bj[0], acc2[i][1] + bj[1],
                            acc2[i][2] + bj[2], acc2[i][3] + bj[3]);
        }
    }
}

// ===========================================================================
// Host launch
// ===========================================================================
extern "C" void kernel_launch(void* const* d_in, const int* in_sizes, int n_in,
                              void* d_out, int out_size) {
    const float* x      = (const float*)d_in[0];
    const int*   ei     = (const int*)  d_in[1];   // [R,2,E]
    const float* Wl     = (const float*)d_in[2];   // [R,768,256]
    const float* Wr     = (const float*)d_in[3];
    const float* att    = (const float*)d_in[4];   // [R,4,64]
    const float* bg     = (const float*)d_in[5];   // [R,256]
    const float* Wrel1  = (const float*)d_in[6];   // [R,256,64]
    const float* Wroot1 = (const float*)d_in[7];
    const float* b1     = (const float*)d_in[8];   // [R,64]
    const float* Wrel2  = (const float*)d_in[9];   // [R,64,64]
    const float* Wroot2 = (const float*)d_in[10];
    const float* b2     = (const float*)d_in[11];  // [R,64]
    float* out = (float*)d_out;                    // [N,R,64]

    float* scratch = nullptr;
    cudaGetSymbolAddress((void**)&scratch, g_scratch);
    float* XLR   = scratch + OFF_XLR;
    float* ea    = scratch + OFF_EA;
    float* h1    = scratch + OFF_H1;
    float* p1    = scratch + OFF_P1;
    float* p2    = scratch + OFF_P2;
    float* denom = scratch + OFF_DENOM;
    float* gat   = scratch + OFF_GAT;
    float* XR    = scratch + OFF_XR;
    float* WT    = scratch + OFF_WT;

    cudaFuncSetAttribute(gemm_xlr_mma_kernel,
                         cudaFuncAttributeMaxDynamicSharedMemorySize, SMEM_GEMM);

    // Preprocess: tf32-round x; transpose+round weights
    round_tf32_kernel<<<4096, 256>>>((const float4*)x, (float4*)XR, NN * DD / 4);
    transpose_w_kernel<<<dim3(24, 16, RN), dim3(32, 8)>>>(Wl, Wr, WT);

    const int M = NN;
    int edgeBlocks    = (EE + NN + 7) / 8;
    int scatterBlocks = (EE + 7) / 8;

    for (int r = 0; r < RN; r++) {
        const int* src = ei + (size_t)r * 2 * EE;
        const int* tgt = src + EE;

        fill_zero_kernel<<<4096, 256>>>((float4*)denom, ZERO_LEN / 4);

        // xl|xr = x @ [Wl|Wr]  (tf32 mma.sync tensor path)
        gemm_xlr_mma_kernel<<<dim3(4, (M + BM - 1) / BM), 256, SMEM_GEMM>>>(
            XR, WT + (size_t)r * 512 * DD, XLR, M);

        // GATv2 edge phase
        gat_logits_kernel<<<edgeBlocks, 256>>>(XLR, src, tgt, att + (size_t)r * HC, ea, denom);
        gat_scatter_kernel<<<edgeBlocks, 256>>>(XLR, src, tgt, ea, denom, gat);

        // h = relu(gat + b_gat) in place
        bias_relu_kernel<<<(M * 64 + 255) / 256, 256>>>(
            (float4*)gat, (const float4*)(bg + (size_t)r * HC), M * 64);

        // GraphConv 1: h1 = relu( scatter((h@Wrel1)[s->t]) + h@Wroot1 + b1 )
        gemm64_dual_kernel<<<(M + 63) / 64, 256>>>(
            gat, Wrel1 + (size_t)r * HC * OO, Wroot1 + (size_t)r * HC * OO,
            b1 + (size_t)r * OO, p1, h1, OO, M, HC);
        scatter_add64_kernel<<<scatterBlocks, 256>>>(p1, src, tgt, h1, OO);
        relu64_kernel<<<(M * 16 + 255) / 256, 256>>>((float4*)h1, M * 16);

        // GraphConv 2 -> out[:, r, :]
        gemm64_dual_kernel<<<(M + 63) / 64, 256>>>(
            h1, Wrel2 + (size_t)r * OO * OO, Wroot2 + (size_t)r * OO * OO,
            b2 + (size_t)r * OO, p2, out + (size_t)r * OO, RN * OO, M, OO);
        scatter_add64_kernel<<<scatterBlocks, 256>>>(p2, src, tgt, out + (size_t)r * OO, RN * OO);
    }
}

// round 4
// speedup vs baseline: 2.3902x; 1.0353x over previous
#include <cuda_runtime.h>
#include <cstdint>
#include <cstddef>

// Problem constants (fixed by the reference)
#define RN 6
#define NN 50000
#define EE 200000
#define DD 768
#define HC 256      // H*C
#define OO 64

// ---------------------------------------------------------------------------
// Scratch layout (floats)
//   XLR0 : [N][512]   xl|xr buffer 0                           25,600,000
//   XLR1 : [N][512]   xl|xr buffer 1                           25,600,000
//   ea   : [E+N][4]   exp(logits)                               1,000,000
//   h1   : [N][64]                                              3,200,000
//   p1   : [N][64]                                              3,200,000
//   p2   : [N][64]                                              3,200,000
//   denom: [N][4]     (zeroed per relation)                       200,000
//   gat  : [N][256]   (zeroed per relation)                    12,800,000
//   XR   : [N][768]   tf32-rounded x                           38,400,000
//   WT   : [R][512][768] tf32-rounded [Wl|Wr]^T                 2,359,296
// ---------------------------------------------------------------------------
__device__ float g_scratch[115559296];

#define OFF_XLR0  0u
#define OFF_XLR1  25600000u
#define OFF_EA    51200000u
#define OFF_H1    52200000u
#define OFF_P1    55400000u
#define OFF_P2    58600000u
#define OFF_DENOM 61800000u
#define OFF_GAT   62000000u
#define OFF_XR    74800000u
#define OFF_WT    113200000u
#define ZERO_LEN  13000000u   // denom + gat contiguous

// ===========================================================================
// PTX helpers (all plain-sm_103-legal: cp.async, ldmatrix, mma.sync, red)
// ===========================================================================
__device__ __forceinline__ uint32_t smem_u32(const void* p) {
    uint32_t a;
    asm("{ .reg .u64 t; cvta.to.shared.u64 t, %1; cvt.u32.u64 %0, t; }"
        : "=r"(a) : "l"(p));
    return a;
}
__device__ __forceinline__ void cp16(uint32_t dst, const void* src, uint32_t sz) {
    asm volatile("cp.async.cg.shared.global [%0], [%1], 16, %2;"
                 :: "r"(dst), "l"(src), "r"(sz) : "memory");
}
__device__ __forceinline__ void cp_commit() {
    asm volatile("cp.async.commit_group;" ::: "memory");
}
__device__ __forceinline__ void cp_wait1() {
    asm volatile("cp.async.wait_group 1;" ::: "memory");
}
#define LDSM4(r0, r1, r2, r3, addr) \
    asm volatile("ldmatrix.sync.aligned.m8n8.x4.shared.b16 {%0,%1,%2,%3}, [%4];" \
                 : "=r"(r0), "=r"(r1), "=r"(r2), "=r"(r3) : "r"(addr))

#define MMA_TF32(d, a, b0, b1) \
    asm volatile("mma.sync.aligned.m16n8k8.row.col.f32.tf32.tf32.f32 " \
                 "{%0,%1,%2,%3}, {%4,%5,%6,%7}, {%8,%9}, {%0,%1,%2,%3};" \
                 : "+f"((d)[0]), "+f"((d)[1]), "+f"((d)[2]), "+f"((d)[3]) \
                 : "r"((a)[0]), "r"((a)[1]), "r"((a)[2]), "r"((a)[3]), \
                   "r"(b0), "r"(b1))

// Vector reductions
__device__ __forceinline__ void red_add_v4(float* p, float a, float b, float c, float d) {
    asm volatile("red.global.add.v4.f32 [%0], {%1,%2,%3,%4};"
                 :: "l"(p), "f"(a), "f"(b), "f"(c), "f"(d) : "memory");
}
__device__ __forceinline__ void red_add_v2(float* p, float a, float b) {
    asm volatile("red.global.add.v2.f32 [%0], {%1,%2};"
                 :: "l"(p), "f"(a), "f"(b) : "memory");
}

// ===========================================================================
// Preprocessing: tf32 rounding + weight transpose
// ===========================================================================
__device__ __forceinline__ float rna_tf32(float v) {
    uint32_t o;
    asm("cvt.rna.tf32.f32 %0, %1;" : "=r"(o) : "f"(v));
    return __uint_as_float(o);
}

__global__ void round_tf32_kernel(const float4* __restrict__ in, float4* __restrict__ out, int n4) {
    int i = blockIdx.x * blockDim.x + threadIdx.x;
    int stride = gridDim.x * blockDim.x;
    for (; i < n4; i += stride) {
        float4 v = in[i];
        v.x = rna_tf32(v.x); v.y = rna_tf32(v.y);
        v.z = rna_tf32(v.z); v.w = rna_tf32(v.w);
        out[i] = v;
    }
}

// WT[r][n][k] = rna(Wl[r][k][n]) for n<256, rna(Wr[r][k][n-256]) otherwise
__global__ void transpose_w_kernel(const float* __restrict__ Wl, const float* __restrict__ Wr,
                                   float* __restrict__ WT) {
    __shared__ float tile[32][33];
    int r = blockIdx.z;
    int k0 = blockIdx.x * 32;   // 24 blocks
    int n0 = blockIdx.y * 32;   // 16 blocks
    const float* W = (n0 < 256) ? Wl : Wr;
    int nc0 = (n0 < 256) ? n0 : (n0 - 256);
    int tx = threadIdx.x, ty = threadIdx.y;  // 32 x 8
#pragma unroll
    for (int i = 0; i < 32; i += 8) {
        float v = W[((size_t)r * DD + k0 + ty + i) * HC + nc0 + tx];
        tile[ty + i][tx] = rna_tf32(v);
    }
    __syncthreads();
#pragma unroll
    for (int i = 0; i < 32; i += 8) {
        WT[((size_t)r * 512 + n0 + ty + i) * DD + k0 + tx] = tile[tx][ty + i];
    }
}

// ===========================================================================
// fill zero
// ===========================================================================
__global__ void fill_zero_kernel(float4* p, int n4) {
    int i = blockIdx.x * blockDim.x + threadIdx.x;
    int stride = gridDim.x * blockDim.x;
    float4 z = make_float4(0.f, 0.f, 0.f, 0.f);
    for (; i < n4; i += stride) p[i] = z;
}

// ===========================================================================
// tf32 mma.sync GEMM: C[M][512] tile = A[M][768] @ B[512][768]^T
// A row-major, B K-major ([n][k]). BM=128 BN=128 BK=32, 3-stage cp.async.
// 256 threads = 8 warps (2 m x 4 n), warp tile 64x32, mma m16n8k8.
// ===========================================================================
#define BM 128
#define BN 128
#define BK 32
#define GSTG 3
#define KIT (DD / BK)               // 24
#define TILE_BYTES (BM * BK * 4)    // 16384
#define SMEM_GEMM (GSTG * 2 * TILE_BYTES + 1024)

__global__ void __launch_bounds__(256, 1)
gemm_xlr_mma_kernel(const float* __restrict__ A, const float* __restrict__ B,
                    float* __restrict__ C, int M) {
    extern __shared__ char sm_raw[];
    uint32_t smbase = (smem_u32(sm_raw) + 1023u) & ~1023u;
    uint32_t sA = smbase;                      // 3 x 16KB
    uint32_t sB = smbase + GSTG * TILE_BYTES;  // 3 x 16KB

    int tid = threadIdx.x;
    int lane = tid & 31, wid = tid >> 5;
    int wm = wid & 1, wn = wid >> 1;
    int M0 = blockIdx.y * BM, N0 = blockIdx.x * BN;

    // --- cp.async mapping: 1024 16B chunks per tile, 4 per thread ---
    uint32_t dstOff[4];
    const float* srcA[4]; uint32_t szA[4];
    const float* srcB[4];
#pragma unroll
    for (int i = 0; i < 4; i++) {
        int lin = tid + i * 256;
        int row = lin >> 3, ch = lin & 7;
        dstOff[i] = row * 128 + ((ch * 16) ^ ((row & 7) * 16));
        int ga = M0 + row;
        szA[i] = (ga < M) ? 16u : 0u;
        srcA[i] = A + (size_t)(ga < M ? ga : 0) * DD + ch * 4;
        srcB[i] = B + (size_t)(N0 + row) * DD + ch * 4;
    }

    // --- ldmatrix address bases (swizzle folded in; XOR ks*32 at use) ---
    uint32_t aOff[4], bOff[2];
#pragma unroll
    for (int mt = 0; mt < 4; mt++) {
        int rowA = wm * 64 + mt * 16 + (lane & 7) + ((lane >> 3) & 1) * 8;
        uint32_t q = (uint32_t)(((lane >> 4) * 16) ^ ((rowA & 7) * 16));
        aOff[mt] = (uint32_t)rowA * 128 + q;
    }
#pragma unroll
    for (int bp = 0; bp < 2; bp++) {
        int rowB = wn * 32 + bp * 16 + (lane & 7) + ((lane >> 4) & 1) * 8;
        uint32_t q = (uint32_t)((((lane >> 3) & 1) * 16) ^ ((rowB & 7) * 16));
        bOff[bp] = (uint32_t)rowB * 128 + q;
    }

    float acc[4][4][4];
#pragma unroll
    for (int mt = 0; mt < 4; mt++)
#pragma unroll
        for (int nt = 0; nt < 4; nt++)
#pragma unroll
            for (int j = 0; j < 4; j++) acc[mt][nt][j] = 0.f;

    // --- prologue: stages 0 and 1 ---
#pragma unroll
    for (int s = 0; s < 2; s++) {
#pragma unroll
        for (int i = 0; i < 4; i++) {
            cp16(sA + s * TILE_BYTES + dstOff[i], srcA[i] + s * BK, szA[i]);
            cp16(sB + s * TILE_BYTES + dstOff[i], srcB[i] + s * BK, 16u);
        }
        cp_commit();
    }

    for (int it = 0; it < KIT; it++) {
        cp_wait1();
        __syncthreads();

        int nx = it + 2;
        if (nx < KIT) {
            int s2 = nx % GSTG;
#pragma unroll
            for (int i = 0; i < 4; i++) {
                cp16(sA + s2 * TILE_BYTES + dstOff[i], srcA[i] + nx * BK, szA[i]);
                cp16(sB + s2 * TILE_BYTES + dstOff[i], srcB[i] + nx * BK, 16u);
            }
        }
        cp_commit();

        int s = it % GSTG;
        uint32_t baseA = sA + s * TILE_BYTES;
        uint32_t baseB = sB + s * TILE_BYTES;
#pragma unroll
        for (int ks = 0; ks < 4; ks++) {
            uint32_t afr[4][4];
            uint32_t bfr[4][2];
#pragma unroll
            for (int mt = 0; mt < 4; mt++)
                LDSM4(afr[mt][0], afr[mt][1], afr[mt][2], afr[mt][3],
                      baseA + (aOff[mt] ^ (uint32_t)(ks * 32)));
#pragma unroll
            for (int bp = 0; bp < 2; bp++) {
                uint32_t r0, r1, r2, r3;
                LDSM4(r0, r1, r2, r3, baseB + (bOff[bp] ^ (uint32_t)(ks * 32)));
                bfr[2 * bp][0] = r0;     bfr[2 * bp][1] = r1;
                bfr[2 * bp + 1][0] = r2; bfr[2 * bp + 1][1] = r3;
            }
#pragma unroll
            for (int mt = 0; mt < 4; mt++)
#pragma unroll
                for (int nt = 0; nt < 4; nt++)
                    MMA_TF32(acc[mt][nt], afr[mt], bfr[nt][0], bfr[nt][1]);
        }
    }

    // --- epilogue ---
    int r = lane >> 2, c = (lane & 3) * 2;
#pragma unroll
    for (int mt = 0; mt < 4; mt++) {
        int grow = M0 + wm * 64 + mt * 16 + r;
#pragma unroll
        for (int nt = 0; nt < 4; nt++) {
            int gcol = N0 + wn * 32 + nt * 8 + c;
            if (grow < M)
                *(float2*)(C + (size_t)grow * 512 + gcol) =
                    make_float2(acc[mt][nt][0], acc[mt][nt][1]);
            if (grow + 8 < M)
                *(float2*)(C + (size_t)(grow + 8) * 512 + gcol) =
                    make_float2(acc[mt][nt][2], acc[mt][nt][3]);
        }
    }
}

// ===========================================================================
// GATv2 edge kernels (validated in R1/R3)
// ===========================================================================
__global__ void gat_logits_kernel(const float* __restrict__ XLR,
                                  const int* __restrict__ src, const int* __restrict__ tgt,
                                  const float* __restrict__ att,
                                  float* __restrict__ ea, float* __restrict__ denom) {
    int warp = (blockIdx.x * blockDim.x + threadIdx.x) >> 5;
    int lane = threadIdx.x & 31;
    int total = EE + NN;
    if (warp >= total) return;
    int s, t;
    if (warp < EE) { s = src[warp]; t = tgt[warp]; }
    else           { s = t = warp - EE; }

    const float* xl = XLR + (size_t)s * 512;
    const float* xr = XLR + (size_t)t * 512 + 256;
    int base = lane * 8;
    float4 l0 = *(const float4*)(xl + base), l1 = *(const float4*)(xl + base + 4);
    float4 r0 = *(const float4*)(xr + base), r1 = *(const float4*)(xr + base + 4);
    float4 a0 = *(const float4*)(att + base), a1 = *(const float4*)(att + base + 4);

#define LRELU(v) ((v) > 0.f ? (v) : 0.2f * (v))
    float sum = LRELU(l0.x + r0.x) * a0.x + LRELU(l0.y + r0.y) * a0.y
              + LRELU(l0.z + r0.z) * a0.z + LRELU(l0.w + r0.w) * a0.w
              + LRELU(l1.x + r1.x) * a1.x + LRELU(l1.y + r1.y) * a1.y
              + LRELU(l1.z + r1.z) * a1.z + LRELU(l1.w + r1.w) * a1.w;
#undef LRELU
    sum += __shfl_xor_sync(0xffffffffu, sum, 1);
    sum += __shfl_xor_sync(0xffffffffu, sum, 2);
    sum += __shfl_xor_sync(0xffffffffu, sum, 4);

    if ((lane & 7) == 0) {
        int h = lane >> 3;
        float e = expf(sum);
        ea[(size_t)warp * 4 + h] = e;
        atomicAdd(denom + (size_t)t * 4 + h, e);
    }
}

__global__ void gat_scatter_kernel(const float* __restrict__ XLR,
                                   const int* __restrict__ src, const int* __restrict__ tgt,
                                   const float* __restrict__ ea, const float* __restrict__ denom,
                                   float* __restrict__ gat) {
    int warp = (blockIdx.x * blockDim.x + threadIdx.x) >> 5;
    int lane = threadIdx.x & 31;
    int total = EE + NN;
    if (warp >= total) return;
    int s, t;
    if (warp < EE) { s = src[warp]; t = tgt[warp]; }
    else           { s = t = warp - EE; }

    int h = lane >> 3;
    float aE = ea[(size_t)warp * 4 + h];
    float dn = denom[(size_t)t * 4 + h];
    float alpha = aE / (dn + 1e-16f);

    int base = lane * 8;
    const float* xl = XLR + (size_t)s * 512 + base;
    float4 v0 = *(const float4*)xl, v1 = *(const float4*)(xl + 4);
    float* dst = gat + (size_t)t * 256 + base;
    red_add_v4(dst,     v0.x * alpha, v0.y * alpha, v0.z * alpha, v0.w * alpha);
    red_add_v4(dst + 4, v1.x * alpha, v1.y * alpha, v1.z * alpha, v1.w * alpha);
}

__global__ void bias_relu_kernel(float4* __restrict__ g, const float4* __restrict__ b, int n4) {
    int i = blockIdx.x * blockDim.x + threadIdx.x;
    if (i >= n4) return;
    float4 v = g[i];
    float4 bb = b[i & 63];
    v.x = fmaxf(v.x + bb.x, 0.f);
    v.y = fmaxf(v.y + bb.y, 0.f);
    v.z = fmaxf(v.z + bb.z, 0.f);
    v.w = fmaxf(v.w + bb.w, 0.f);
    g[i] = v;
}

// scatter: dst[t][0:64] += p[s][0:64], dst row stride ldd
__global__ void scatter_add64_kernel(const float* __restrict__ p,
                                     const int* __restrict__ src, const int* __restrict__ tgt,
                                     float* __restrict__ dst, int ldd) {
    int warp = (blockIdx.x * blockDim.x + threadIdx.x) >> 5;
    int lane = threadIdx.x & 31;
    if (warp >= EE) return;
    int s = src[warp], t = tgt[warp];
    float2 v = *(const float2*)(p + (size_t)s * 64 + lane * 2);
    red_add_v2(dst + (size_t)t * ldd + lane * 2, v.x, v.y);
}

// ===========================================================================
// Dual small GEMM: C1 = A@B1 (no bias, ldc 64); C2 = A@B2 + bias (ldc param)
// A: [M][K] row-major, B: [K][64]. Optional relu applied to A on load.
// ===========================================================================
__global__ void __launch_bounds__(256)
gemm64_dual_kernel(const float* __restrict__ A,
                   const float* __restrict__ B1, const float* __restrict__ B2,
                   const float* __restrict__ bias,
                   float* __restrict__ C1, float* __restrict__ C2,
                   int ldc2, int M, int K, int relu_a) {
    __shared__ float As[32][68];
    __shared__ float B1s[32][64];
    __shared__ float B2s[32][64];
    int m0 = blockIdx.x * 64;
    int tid = threadIdx.x;
    int tx = tid & 15, ty = tid >> 4;
    float acc1[4][4], acc2[4][4];
#pragma unroll
    for (int i = 0; i < 4; i++)
#pragma unroll
        for (int j = 0; j < 4; j++) { acc1[i][j] = 0.f; acc2[i][j] = 0.f; }

    for (int k0 = 0; k0 < K; k0 += 32) {
#pragma unroll
        for (int l = 0; l < 2; l++) {
            int lin = tid + l * 256;
            int row = lin >> 3, kc = (lin & 7) * 4;
            float4 v = make_float4(0.f, 0.f, 0.f, 0.f);
            int gm = m0 + row;
            if (gm < M) v = *(const float4*)(A + (size_t)gm * K + k0 + kc);
            if (relu_a) {
                v.x = fmaxf(v.x, 0.f); v.y = fmaxf(v.y, 0.f);
                v.z = fmaxf(v.z, 0.f); v.w = fmaxf(v.w, 0.f);
            }
            As[kc + 0][row] = v.x; As[kc + 1][row] = v.y;
            As[kc + 2][row] = v.z; As[kc + 3][row] = v.w;

            int br = lin >> 4, bc = (lin & 15) * 4;
            *(float4*)&B1s[br][bc] = *(const float4*)(B1 + (size_t)(k0 + br) * 64 + bc);
            *(float4*)&B2s[br][bc] = *(const float4*)(B2 + (size_t)(k0 + br) * 64 + bc);
        }
        __syncthreads();
#pragma unroll
        for (int k = 0; k < 32; k++) {
            float a[4], b1v[4], b2v[4];
#pragma unroll
            for (int i = 0; i < 4; i++) a[i] = As[k][ty * 4 + i];
#pragma unroll
            for (int j = 0; j < 4; j++) { b1v[j] = B1s[k][tx * 4 + j]; b2v[j] = B2s[k][tx * 4 + j]; }
#pragma unroll
            for (int i = 0; i < 4; i++)
#pragma unroll
                for (int j = 0; j < 4; j++) {
                    acc1[i][j] += a[i] * b1v[j];
                    acc2[i][j] += a[i] * b2v[j];
                }
        }
        __syncthreads();
    }

    float bj[4];
#pragma unroll
    for (int j = 0; j < 4; j++) bj[j] = bias[tx * 4 + j];
#pragma unroll
    for (int i = 0; i < 4; i++) {
        int gm = m0 + ty * 4 + i;
        if (gm < M) {
            *(float4*)(C1 + (size_t)gm * 64 + tx * 4) =
                make_float4(acc1[i][0], acc1[i][1], acc1[i][2], acc1[i][3]);
            *(float4*)(C2 + (size_t)gm * ldc2 + tx * 4) =
                make_float4(acc2[i][0] + bj[0], acc2[i][1] + bj[1],
                            acc2[i][2] + bj[2], acc2[i][3] + bj[3]);
        }
    }
}

// ===========================================================================
// Host launch: fork-join two streams under graph capture.
//   stream G (side): big tf32 GEMM for relation r into XLR[r&1]
//   stream M (main): everything else for relation r
// ===========================================================================
extern "C" void kernel_launch(void* const* d_in, const int* in_sizes, int n_in,
                              void* d_out, int out_size) {
    const float* x      = (const float*)d_in[0];
    const int*   ei     = (const int*)  d_in[1];   // [R,2,E]
    const float* Wl     = (const float*)d_in[2];   // [R,768,256]
    const float* Wr     = (const float*)d_in[3];
    const float* att    = (const float*)d_in[4];   // [R,4,64]
    const float* bg     = (const float*)d_in[5];   // [R,256]
    const float* Wrel1  = (const float*)d_in[6];   // [R,256,64]
    const float* Wroot1 = (const float*)d_in[7];
    const float* b1     = (const float*)d_in[8];   // [R,64]
    const float* Wrel2  = (const float*)d_in[9];   // [R,64,64]
    const float* Wroot2 = (const float*)d_in[10];
    const float* b2     = (const float*)d_in[11];  // [R,64]
    float* out = (float*)d_out;                    // [N,R,64]

    float* scratch = nullptr;
    cudaGetSymbolAddress((void**)&scratch, g_scratch);
    float* XLRbuf[2] = { scratch + OFF_XLR0, scratch + OFF_XLR1 };
    float* ea    = scratch + OFF_EA;
    float* h1    = scratch + OFF_H1;
    float* p1    = scratch + OFF_P1;
    float* p2    = scratch + OFF_P2;
    float* denom = scratch + OFF_DENOM;
    float* gat   = scratch + OFF_GAT;
    float* XR    = scratch + OFF_XR;
    float* WT    = scratch + OFF_WT;

    // One-time resources (host-side objects only; no device allocation).
    static cudaStream_t sG = nullptr;
    static cudaEvent_t evPre, evG[RN], evFree[RN];
    if (!sG) {
        cudaStreamCreateWithFlags(&sG, cudaStreamNonBlocking);
        cudaEventCreateWithFlags(&evPre, cudaEventDisableTiming);
        for (int r = 0; r < RN; r++) {
            cudaEventCreateWithFlags(&evG[r], cudaEventDisableTiming);
            cudaEventCreateWithFlags(&evFree[r], cudaEventDisableTiming);
        }
        cudaFuncSetAttribute(gemm_xlr_mma_kernel,
                             cudaFuncAttributeMaxDynamicSharedMemorySize, SMEM_GEMM);
    }

    const int M = NN;
    int edgeBlocks    = (EE + NN + 7) / 8;
    int scatterBlocks = (EE + 7) / 8;
    cudaStream_t sM = 0;  // main (capture-origin) stream

    // Preprocess on main stream, then fork side stream.
    round_tf32_kernel<<<4096, 256, 0, sM>>>((const float4*)x, (float4*)XR, NN * DD / 4);
    transpose_w_kernel<<<dim3(24, 16, RN), dim3(32, 8), 0, sM>>>(Wl, Wr, WT);
    cudaEventRecord(evPre, sM);
    cudaStreamWaitEvent(sG, evPre, 0);

    for (int r = 0; r < RN; r++) {
        const int* src = ei + (size_t)r * 2 * EE;
        const int* tgt = src + EE;
        float* XLR = XLRbuf[r & 1];

        // --- side stream: big GEMM for relation r ---
        if (r >= 2) cudaStreamWaitEvent(sG, evFree[r - 2], 0);  // buffer reuse dep
        gemm_xlr_mma_kernel<<<dim3(4, (M + BM - 1) / BM), 256, SMEM_GEMM, sG>>>(
            XR, WT + (size_t)r * 512 * DD, XLR, M);
        cudaEventRecord(evG[r], sG);

        // --- main stream: relation r pipeline ---
        fill_zero_kernel<<<4096, 256, 0, sM>>>((float4*)denom, ZERO_LEN / 4);
        cudaStreamWaitEvent(sM, evG[r], 0);

        gat_logits_kernel<<<edgeBlocks, 256, 0, sM>>>(XLR, src, tgt,
                                                      att + (size_t)r * HC, ea, denom);
        gat_scatter_kernel<<<edgeBlocks, 256, 0, sM>>>(XLR, src, tgt, ea, denom, gat);
        cudaEventRecord(evFree[r], sM);  // last reader of XLRbuf[r&1]

        bias_relu_kernel<<<(M * 64 + 255) / 256, 256, 0, sM>>>(
            (float4*)gat, (const float4*)(bg + (size_t)r * HC), M * 64);

        // GraphConv 1: h1 = relu( scatter((h@Wrel1)[s->t]) + h@Wroot1 + b1 )
        gemm64_dual_kernel<<<(M + 63) / 64, 256, 0, sM>>>(
            gat, Wrel1 + (size_t)r * HC * OO, Wroot1 + (size_t)r * HC * OO,
            b1 + (size_t)r * OO, p1, h1, OO, M, HC, 0);
        scatter_add64_kernel<<<scatterBlocks, 256, 0, sM>>>(p1, src, tgt, h1, OO);

        // GraphConv 2 -> out[:, r, :]   (relu of h1 applied on A-load)
        gemm64_dual_kernel<<<(M + 63) / 64, 256, 0, sM>>>(
            h1, Wrel2 + (size_t)r * OO * OO, Wroot2 + (size_t)r * OO * OO,
            b2 + (size_t)r * OO, p2, out + (size_t)r * OO, RN * OO, M, OO, 1);
        scatter_add64_kernel<<<scatterBlocks, 256, 0, sM>>>(p2, src, tgt,
                                                            out + (size_t)r * OO, RN * OO);
    }
    // Side stream's last node (gemm r=5 + evG[5]) is already joined into sM
    // via the cudaStreamWaitEvent(sM, evG[5]) above — graph is fully joined.
}

// round 5
// speedup vs baseline: 2.5404x; 1.0628x over previous
#include <cuda_runtime.h>
#include <cstdint>
#include <cstddef>

// Problem constants (fixed by the reference)
#define RN 6
#define NN 50000
#define EE 200000
#define DD 768
#define HC 256      // H*C
#define OO 64

// ---------------------------------------------------------------------------
// Scratch layout (floats)
//   XLR0 : [N][512]   xl|xr buffer 0                           25,600,000
//   XLR1 : [N][512]   xl|xr buffer 1                           25,600,000
//   h1   : [N][64]                                              3,200,000
//   p1   : [N][64]                                              3,200,000
//   p2   : [N][64]                                              3,200,000
//   denom: [N][4]     (zeroed per relation)                       200,000
//   gat  : [N][256]   unnormalized GAT accumulator             12,800,000
//   XR   : [N][768]   tf32-rounded x                           38,400,000
//   WT   : [R][512][768] tf32-rounded [Wl|Wr]^T                 2,359,296
// ---------------------------------------------------------------------------
__device__ float g_scratch[114559296];

#define OFF_XLR0  0u
#define OFF_XLR1  25600000u
#define OFF_H1    51200000u
#define OFF_P1    54400000u
#define OFF_P2    57600000u
#define OFF_DENOM 60800000u
#define OFF_GAT   61000000u
#define OFF_XR    73800000u
#define OFF_WT    112200000u
#define ZERO_LEN  13000000u   // denom + gat contiguous

// ===========================================================================
// PTX helpers (all plain-sm_103-legal: cp.async, ldmatrix, mma.sync, red)
// ===========================================================================
__device__ __forceinline__ uint32_t smem_u32(const void* p) {
    uint32_t a;
    asm("{ .reg .u64 t; cvta.to.shared.u64 t, %1; cvt.u32.u64 %0, t; }"
        : "=r"(a) : "l"(p));
    return a;
}
__device__ __forceinline__ void cp16(uint32_t dst, const void* src, uint32_t sz) {
    asm volatile("cp.async.cg.shared.global [%0], [%1], 16, %2;"
                 :: "r"(dst), "l"(src), "r"(sz) : "memory");
}
__device__ __forceinline__ void cp_commit() {
    asm volatile("cp.async.commit_group;" ::: "memory");
}
__device__ __forceinline__ void cp_wait2() {
    asm volatile("cp.async.wait_group 2;" ::: "memory");
}
#define LDSM4(r0, r1, r2, r3, addr) \
    asm volatile("ldmatrix.sync.aligned.m8n8.x4.shared.b16 {%0,%1,%2,%3}, [%4];" \
                 : "=r"(r0), "=r"(r1), "=r"(r2), "=r"(r3) : "r"(addr))

#define MMA_TF32(d, a, b0, b1) \
    asm volatile("mma.sync.aligned.m16n8k8.row.col.f32.tf32.tf32.f32 " \
                 "{%0,%1,%2,%3}, {%4,%5,%6,%7}, {%8,%9}, {%0,%1,%2,%3};" \
                 : "+f"((d)[0]), "+f"((d)[1]), "+f"((d)[2]), "+f"((d)[3]) \
                 : "r"((a)[0]), "r"((a)[1]), "r"((a)[2]), "r"((a)[3]), \
                   "r"(b0), "r"(b1))

// Vector reductions
__device__ __forceinline__ void red_add_v4(float* p, float a, float b, float c, float d) {
    asm volatile("red.global.add.v4.f32 [%0], {%1,%2,%3,%4};"
                 :: "l"(p), "f"(a), "f"(b), "f"(c), "f"(d) : "memory");
}
__device__ __forceinline__ void red_add_v2(float* p, float a, float b) {
    asm volatile("red.global.add.v2.f32 [%0], {%1,%2};"
                 :: "l"(p), "f"(a), "f"(b) : "memory");
}

// ===========================================================================
// Preprocessing: tf32 rounding + weight transpose
// ===========================================================================
__device__ __forceinline__ float rna_tf32(float v) {
    uint32_t o;
    asm("cvt.rna.tf32.f32 %0, %1;" : "=r"(o) : "f"(v));
    return __uint_as_float(o);
}

__global__ void round_tf32_kernel(const float4* __restrict__ in, float4* __restrict__ out, int n4) {
    int i = blockIdx.x * blockDim.x + threadIdx.x;
    int stride = gridDim.x * blockDim.x;
    for (; i < n4; i += stride) {
        float4 v = in[i];
        v.x = rna_tf32(v.x); v.y = rna_tf32(v.y);
        v.z = rna_tf32(v.z); v.w = rna_tf32(v.w);
        out[i] = v;
    }
}

// WT[r][n][k] = rna(Wl[r][k][n]) for n<256, rna(Wr[r][k][n-256]) otherwise
__global__ void transpose_w_kernel(const float* __restrict__ Wl, const float* __restrict__ Wr,
                                   float* __restrict__ WT) {
    __shared__ float tile[32][33];
    int r = blockIdx.z;
    int k0 = blockIdx.x * 32;   // 24 blocks
    int n0 = blockIdx.y * 32;   // 16 blocks
    const float* W = (n0 < 256) ? Wl : Wr;
    int nc0 = (n0 < 256) ? n0 : (n0 - 256);
    int tx = threadIdx.x, ty = threadIdx.y;  // 32 x 8
#pragma unroll
    for (int i = 0; i < 32; i += 8) {
        float v = W[((size_t)r * DD + k0 + ty + i) * HC + nc0 + tx];
        tile[ty + i][tx] = rna_tf32(v);
    }
    __syncthreads();
#pragma unroll
    for (int i = 0; i < 32; i += 8) {
        WT[((size_t)r * 512 + n0 + ty + i) * DD + k0 + tx] = tile[tx][ty + i];
    }
}

// ===========================================================================
// fill zero
// ===========================================================================
__global__ void fill_zero_kernel(float4* p, int n4) {
    int i = blockIdx.x * blockDim.x + threadIdx.x;
    int stride = gridDim.x * blockDim.x;
    float4 z = make_float4(0.f, 0.f, 0.f, 0.f);
    for (; i < n4; i += stride) p[i] = z;
}

// ===========================================================================
// tf32 mma.sync GEMM: C[M][512] tile = A[M][768] @ B[512][768]^T
// A row-major, B K-major ([n][k]). BM=128 BN=128 BK=32, 4-stage cp.async.
// 256 threads = 8 warps (2 m x 4 n), warp tile 64x32, mma m16n8k8.
// ===========================================================================
#define BM 128
#define BN 128
#define BK 32
#define GSTG 4
#define KIT (DD / BK)               // 24
#define TILE_BYTES (BM * BK * 4)    // 16384
#define SMEM_GEMM (GSTG * 2 * TILE_BYTES + 1024)

__global__ void __launch_bounds__(256, 1)
gemm_xlr_mma_kernel(const float* __restrict__ A, const float* __restrict__ B,
                    float* __restrict__ C, int M) {
    extern __shared__ char sm_raw[];
    uint32_t smbase = (smem_u32(sm_raw) + 1023u) & ~1023u;
    uint32_t sA = smbase;                      // 4 x 16KB
    uint32_t sB = smbase + GSTG * TILE_BYTES;  // 4 x 16KB

    int tid = threadIdx.x;
    int lane = tid & 31, wid = tid >> 5;
    int wm = wid & 1, wn = wid >> 1;
    int M0 = blockIdx.y * BM, N0 = blockIdx.x * BN;

    // --- cp.async mapping: 1024 16B chunks per tile, 4 per thread ---
    uint32_t dstOff[4];
    const float* srcA[4]; uint32_t szA[4];
    const float* srcB[4];
#pragma unroll
    for (int i = 0; i < 4; i++) {
        int lin = tid + i * 256;
        int row = lin >> 3, ch = lin & 7;
        dstOff[i] = row * 128 + ((ch * 16) ^ ((row & 7) * 16));
        int ga = M0 + row;
        szA[i] = (ga < M) ? 16u : 0u;
        srcA[i] = A + (size_t)(ga < M ? ga : 0) * DD + ch * 4;
        srcB[i] = B + (size_t)(N0 + row) * DD + ch * 4;
    }

    // --- ldmatrix address bases (swizzle folded in; XOR ks*32 at use) ---
    uint32_t aOff[4], bOff[2];
#pragma unroll
    for (int mt = 0; mt < 4; mt++) {
        int rowA = wm * 64 + mt * 16 + (lane & 7) + ((lane >> 3) & 1) * 8;
        uint32_t q = (uint32_t)(((lane >> 4) * 16) ^ ((rowA & 7) * 16));
        aOff[mt] = (uint32_t)rowA * 128 + q;
    }
#pragma unroll
    for (int bp = 0; bp < 2; bp++) {
        int rowB = wn * 32 + bp * 16 + (lane & 7) + ((lane >> 4) & 1) * 8;
        uint32_t q = (uint32_t)((((lane >> 3) & 1) * 16) ^ ((rowB & 7) * 16));
        bOff[bp] = (uint32_t)rowB * 128 + q;
    }

    float acc[4][4][4];
#pragma unroll
    for (int mt = 0; mt < 4; mt++)
#pragma unroll
        for (int nt = 0; nt < 4; nt++)
#pragma unroll
            for (int j = 0; j < 4; j++) acc[mt][nt][j] = 0.f;

    // --- prologue: stages 0..2 ---
#pragma unroll
    for (int s = 0; s < 3; s++) {
#pragma unroll
        for (int i = 0; i < 4; i++) {
            cp16(sA + s * TILE_BYTES + dstOff[i], srcA[i] + s * BK, szA[i]);
            cp16(sB + s * TILE_BYTES + dstOff[i], srcB[i] + s * BK, 16u);
        }
        cp_commit();
    }

    for (int it = 0; it < KIT; it++) {
        cp_wait2();
        __syncthreads();

        int nx = it + 3;
        if (nx < KIT) {
            int s2 = nx % GSTG;
#pragma unroll
            for (int i = 0; i < 4; i++) {
                cp16(sA + s2 * TILE_BYTES + dstOff[i], srcA[i] + nx * BK, szA[i]);
                cp16(sB + s2 * TILE_BYTES + dstOff[i], srcB[i] + nx * BK, 16u);
            }
        }
        cp_commit();

        int s = it % GSTG;
        uint32_t baseA = sA + s * TILE_BYTES;
        uint32_t baseB = sB + s * TILE_BYTES;
#pragma unroll
        for (int ks = 0; ks < 4; ks++) {
            uint32_t afr[4][4];
            uint32_t bfr[4][2];
#pragma unroll
            for (int mt = 0; mt < 4; mt++)
                LDSM4(afr[mt][0], afr[mt][1], afr[mt][2], afr[mt][3],
                      baseA + (aOff[mt] ^ (uint32_t)(ks * 32)));
#pragma unroll
            for (int bp = 0; bp < 2; bp++) {
                uint32_t r0, r1, r2, r3;
                LDSM4(r0, r1, r2, r3, baseB + (bOff[bp] ^ (uint32_t)(ks * 32)));
                bfr[2 * bp][0] = r0;     bfr[2 * bp][1] = r1;
                bfr[2 * bp + 1][0] = r2; bfr[2 * bp + 1][1] = r3;
            }
#pragma unroll
            for (int mt = 0; mt < 4; mt++)
#pragma unroll
                for (int nt = 0; nt < 4; nt++)
                    MMA_TF32(acc[mt][nt], afr[mt], bfr[nt][0], bfr[nt][1]);
        }
    }

    // --- epilogue ---
    int r = lane >> 2, c = (lane & 3) * 2;
#pragma unroll
    for (int mt = 0; mt < 4; mt++) {
        int grow = M0 + wm * 64 + mt * 16 + r;
#pragma unroll
        for (int nt = 0; nt < 4; nt++) {
            int gcol = N0 + wn * 32 + nt * 8 + c;
            if (grow < M)
                *(float2*)(C + (size_t)grow * 512 + gcol) =
                    make_float2(acc[mt][nt][0], acc[mt][nt][1]);
            if (grow + 8 < M)
                *(float2*)(C + (size_t)(grow + 8) * 512 + gcol) =
                    make_float2(acc[mt][nt][2], acc[mt][nt][3]);
        }
    }
}

// ===========================================================================
// Fused GATv2 edge pass: per edge, compute e = exp(logit) once and scatter
// UNNORMALIZED messages:  gat[t] += e * xl[s],  denom[t][h] += e.
// Normalization happens later in norm_bias_relu (denom is per (t,h) constant).
// One warp per edge; lane handles 8 contiguous channels (head = lane>>3);
// butterfly reduce leaves full head-sum in every lane of the 8-group.
// ===========================================================================
__global__ void gat_edge_kernel(const float* __restrict__ XLR,
                                const int* __restrict__ src, const int* __restrict__ tgt,
                                const float* __restrict__ att,
                                float* __restrict__ gat, float* __restrict__ denom) {
    int warp = (blockIdx.x * blockDim.x + threadIdx.x) >> 5;
    int lane = threadIdx.x & 31;
    int total = EE + NN;
    if (warp >= total) return;
    int s, t;
    if (warp < EE) { s = src[warp]; t = tgt[warp]; }
    else           { s = t = warp - EE; }

    const float* xl = XLR + (size_t)s * 512;
    const float* xr = XLR + (size_t)t * 512 + 256;
    int base = lane * 8;
    float4 l0 = *(const float4*)(xl + base), l1 = *(const float4*)(xl + base + 4);
    float4 r0 = *(const float4*)(xr + base), r1 = *(const float4*)(xr + base + 4);
    float4 a0 = *(const float4*)(att + base), a1 = *(const float4*)(att + base + 4);

#define LRELU(v) ((v) > 0.f ? (v) : 0.2f * (v))
    float sum = LRELU(l0.x + r0.x) * a0.x + LRELU(l0.y + r0.y) * a0.y
              + LRELU(l0.z + r0.z) * a0.z + LRELU(l0.w + r0.w) * a0.w
              + LRELU(l1.x + r1.x) * a1.x + LRELU(l1.y + r1.y) * a1.y
              + LRELU(l1.z + r1.z) * a1.z + LRELU(l1.w + r1.w) * a1.w;
#undef LRELU
    sum += __shfl_xor_sync(0xffffffffu, sum, 1);
    sum += __shfl_xor_sync(0xffffffffu, sum, 2);
    sum += __shfl_xor_sync(0xffffffffu, sum, 4);

    float e = expf(sum);  // full head-sum present in every lane of the 8-group

    float* dst = gat + (size_t)t * 256 + base;
    red_add_v4(dst,     l0.x * e, l0.y * e, l0.z * e, l0.w * e);
    red_add_v4(dst + 4, l1.x * e, l1.y * e, l1.z * e, l1.w * e);
    if ((lane & 7) == 0)
        atomicAdd(denom + (size_t)t * 4 + (lane >> 3), e);
}

// ===========================================================================
// h = relu(gat / denom[head] + b_gat)  in place (per-float4: 4 channels,
// all within one head since head spans 64 channels = 16 float4s)
// ===========================================================================
__global__ void norm_bias_relu_kernel(float4* __restrict__ g, const float* __restrict__ denom,
                                      const float4* __restrict__ b, int n4) {
    int i = blockIdx.x * blockDim.x + threadIdx.x;
    if (i >= n4) return;
    int n = i >> 6;              // node
    int head = (i >> 4) & 3;     // (i & 63) / 16
    float d = denom[n * 4 + head] + 1e-16f;
    float rd = __frcp_rn(d);
    float4 v = g[i];
    float4 bb = b[i & 63];
    v.x = fmaxf(v.x * rd + bb.x, 0.f);
    v.y = fmaxf(v.y * rd + bb.y, 0.f);
    v.z = fmaxf(v.z * rd + bb.z, 0.f);
    v.w = fmaxf(v.w * rd + bb.w, 0.f);
    g[i] = v;
}

// scatter: dst[t][0:64] += p[s][0:64], dst row stride ldd
__global__ void scatter_add64_kernel(const float* __restrict__ p,
                                     const int* __restrict__ src, const int* __restrict__ tgt,
                                     float* __restrict__ dst, int ldd) {
    int warp = (blockIdx.x * blockDim.x + threadIdx.x) >> 5;
    int lane = threadIdx.x & 31;
    if (warp >= EE) return;
    int s = src[warp], t = tgt[warp];
    float2 v = *(const float2*)(p + (size_t)s * 64 + lane * 2);
    red_add_v2(dst + (size_t)t * ldd + lane * 2, v.x, v.y);
}

// ===========================================================================
// Dual small GEMM: C1 = A@B1 (no bias, ldc 64); C2 = A@B2 + bias (ldc param)
// A: [M][K] row-major, B: [K][64]. Optional relu applied to A on load.
// ===========================================================================
__global__ void __launch_bounds__(256)
gemm64_dual_kernel(const float* __restrict__ A,
                   const float* __restrict__ B1, const float* __restrict__ B2,
                   const float* __restrict__ bias,
                   float* __restrict__ C1, float* __restrict__ C2,
                   int ldc2, int M, int K, int relu_a) {
    __shared__ float As[32][68];
    __shared__ float B1s[32][64];
    __shared__ float B2s[32][64];
    int m0 = blockIdx.x * 64;
    int tid = threadIdx.x;
    int tx = tid & 15, ty = tid >> 4;
    float acc1[4][4], acc2[4][4];
#pragma unroll
    for (int i = 0; i < 4; i++)
#pragma unroll
        for (int j = 0; j < 4; j++) { acc1[i][j] = 0.f; acc2[i][j] = 0.f; }

    for (int k0 = 0; k0 < K; k0 += 32) {
#pragma unroll
        for (int l = 0; l < 2; l++) {
            int lin = tid + l * 256;
            int row = lin >> 3, kc = (lin & 7) * 4;
            float4 v = make_float4(0.f, 0.f, 0.f, 0.f);
            int gm = m0 + row;
            if (gm < M) v = *(const float4*)(A + (size_t)gm * K + k0 + kc);
            if (relu_a) {
                v.x = fmaxf(v.x, 0.f); v.y = fmaxf(v.y, 0.f);
                v.z = fmaxf(v.z, 0.f); v.w = fmaxf(v.w, 0.f);
            }
            As[kc + 0][row] = v.x; As[kc + 1][row] = v.y;
            As[kc + 2][row] = v.z; As[kc + 3][row] = v.w;

            int br = lin >> 4, bc = (lin & 15) * 4;
            *(float4*)&B1s[br][bc] = *(const float4*)(B1 + (size_t)(k0 + br) * 64 + bc);
            *(float4*)&B2s[br][bc] = *(const float4*)(B2 + (size_t)(k0 + br) * 64 + bc);
        }
        __syncthreads();
#pragma unroll
        for (int k = 0; k < 32; k++) {
            float a[4], b1v[4], b2v[4];
#pragma unroll
            for (int i = 0; i < 4; i++) a[i] = As[k][ty * 4 + i];
#pragma unroll
            for (int j = 0; j < 4; j++) { b1v[j] = B1s[k][tx * 4 + j]; b2v[j] = B2s[k][tx * 4 + j]; }
#pragma unroll
            for (int i = 0; i < 4; i++)
#pragma unroll
                for (int j = 0; j < 4; j++) {
                    acc1[i][j] += a[i] * b1v[j];
                    acc2[i][j] += a[i] * b2v[j];
                }
        }
        __syncthreads();
    }

    float bj[4];
#pragma unroll
    for (int j = 0; j < 4; j++) bj[j] = bias[tx * 4 + j];
#pragma unroll
    for (int i = 0; i < 4; i++) {
        int gm = m0 + ty * 4 + i;
        if (gm < M) {
            *(float4*)(C1 + (size_t)gm * 64 + tx * 4) =
                make_float4(acc1[i][0], acc1[i][1], acc1[i][2], acc1[i][3]);
            *(float4*)(C2 + (size_t)gm * ldc2 + tx * 4) =
                make_float4(acc2[i][0] + bj[0], acc2[i][1] + bj[1],
                            acc2[i][2] + bj[2], acc2[i][3] + bj[3]);
        }
    }
}

// ===========================================================================
// Host launch: fork-join two streams under graph capture.
// ===========================================================================
extern "C" void kernel_launch(void* const* d_in, const int* in_sizes, int n_in,
                              void* d_out, int out_size) {
    const float* x      = (const float*)d_in[0];
    const int*   ei     = (const int*)  d_in[1];   // [R,2,E]
    const float* Wl     = (const float*)d_in[2];   // [R,768,256]
    const float* Wr     = (const float*)d_in[3];
    const float* att    = (const float*)d_in[4];   // [R,4,64]
    const float* bg     = (const float*)d_in[5];   // [R,256]
    const float* Wrel1  = (const float*)d_in[6];   // [R,256,64]
    const float* Wroot1 = (const float*)d_in[7];
    const float* b1     = (const float*)d_in[8];   // [R,64]
    const float* Wrel2  = (const float*)d_in[9];   // [R,64,64]
    const float* Wroot2 = (const float*)d_in[10];
    const float* b2     = (const float*)d_in[11];  // [R,64]
    float* out = (float*)d_out;                    // [N,R,64]

    float* scratch = nullptr;
    cudaGetSymbolAddress((void**)&scratch, g_scratch);
    float* XLRbuf[2] = { scratch + OFF_XLR0, scratch + OFF_XLR1 };
    float* h1    = scratch + OFF_H1;
    float* p1    = scratch + OFF_P1;
    float* p2    = scratch + OFF_P2;
    float* denom = scratch + OFF_DENOM;
    float* gat   = scratch + OFF_GAT;
    float* XR    = scratch + OFF_XR;
    float* WT    = scratch + OFF_WT;

    // One-time resources (host-side objects only; no device allocation).
    static cudaStream_t sG = nullptr;
    static cudaEvent_t evPre, evG[RN], evFree[RN];
    if (!sG) {
        cudaStreamCreateWithFlags(&sG, cudaStreamNonBlocking);
        cudaEventCreateWithFlags(&evPre, cudaEventDisableTiming);
        for (int r = 0; r < RN; r++) {
            cudaEventCreateWithFlags(&evG[r], cudaEventDisableTiming);
            cudaEventCreateWithFlags(&evFree[r], cudaEventDisableTiming);
        }
        cudaFuncSetAttribute(gemm_xlr_mma_kernel,
                             cudaFuncAttributeMaxDynamicSharedMemorySize, SMEM_GEMM);
    }

    const int M = NN;
    int edgeBlocks    = (EE + NN + 7) / 8;
    int scatterBlocks = (EE + 7) / 8;
    cudaStream_t sM = 0;  // main (capture-origin) stream

    // Preprocess on main stream, then fork side stream.
    round_tf32_kernel<<<4096, 256, 0, sM>>>((const float4*)x, (float4*)XR, NN * DD / 4);
    transpose_w_kernel<<<dim3(24, 16, RN), dim3(32, 8), 0, sM>>>(Wl, Wr, WT);
    cudaEventRecord(evPre, sM);
    cudaStreamWaitEvent(sG, evPre, 0);

    for (int r = 0; r < RN; r++) {
        const int* src = ei + (size_t)r * 2 * EE;
        const int* tgt = src + EE;
        float* XLR = XLRbuf[r & 1];

        // --- side stream: big GEMM for relation r ---
        if (r >= 2) cudaStreamWaitEvent(sG, evFree[r - 2], 0);  // buffer reuse dep
        gemm_xlr_mma_kernel<<<dim3(4, (M + BM - 1) / BM), 256, SMEM_GEMM, sG>>>(
            XR, WT + (size_t)r * 512 * DD, XLR, M);
        cudaEventRecord(evG[r], sG);

        // --- main stream: relation r pipeline ---
        fill_zero_kernel<<<4096, 256, 0, sM>>>((float4*)denom, ZERO_LEN / 4);
        cudaStreamWaitEvent(sM, evG[r], 0);

        // fused edge pass: unnormalized scatter + denom
        gat_edge_kernel<<<edgeBlocks, 256, 0, sM>>>(XLR, src, tgt,
                                                    att + (size_t)r * HC, gat, denom);
        cudaEventRecord(evFree[r], sM);  // last reader of XLRbuf[r&1]

        // h = relu(gat/denom + b_gat) in place
        norm_bias_relu_kernel<<<(M * 64 + 255) / 256, 256, 0, sM>>>(
            (float4*)gat, denom, (const float4*)(bg + (size_t)r * HC), M * 64);

        // GraphConv 1: h1 = relu( scatter((h@Wrel1)[s->t]) + h@Wroot1 + b1 )
        gemm64_dual_kernel<<<(M + 63) / 64, 256, 0, sM>>>(
            gat, Wrel1 + (size_t)r * HC * OO, Wroot1 + (size_t)r * HC * OO,
            b1 + (size_t)r * OO, p1, h1, OO, M, HC, 0);
        scatter_add64_kernel<<<scatterBlocks, 256, 0, sM>>>(p1, src, tgt, h1, OO);

        // GraphConv 2 -> out[:, r, :]   (relu of h1 applied on A-load)
        gemm64_dual_kernel<<<(M + 63) / 64, 256, 0, sM>>>(
            h1, Wrel2 + (size_t)r * OO * OO, Wroot2 + (size_t)r * OO * OO,
            b2 + (size_t)r * OO, p2, out + (size_t)r * OO, RN * OO, M, OO, 1);
        scatter_add64_kernel<<<scatterBlocks, 256, 0, sM>>>(p2, src, tgt,
                                                            out + (size_t)r * OO, RN * OO);
    }
}

// round 6
// speedup vs baseline: 2.9597x; 1.1650x over previous
#include <cuda_runtime.h>
#include <cstdint>
#include <cstddef>

// Problem constants (fixed by the reference)
#define RN 6
#define NN 50000
#define EE 200000
#define DD 768
#define HC 256      // H*C
#define OO 64

// ---------------------------------------------------------------------------
// Scratch layout (floats)
//   XLR0 : [N][512]   xl|xr buffer 0                           25,600,000
//   XLR1 : [N][512]   xl|xr buffer 1                           25,600,000
//   h    : [N][256]   GAT output (relu'd)                      12,800,000
//   h1   : [N][64]                                              3,200,000
//   p1   : [N][64]                                              3,200,000
//   p2   : [N][64]                                              3,200,000
//   XR   : [N][768]   tf32-rounded x                           38,400,000
//   WT   : [R][512][768] tf32-rounded [Wl|Wr]^T                 2,359,296
// ---------------------------------------------------------------------------
__device__ float g_scratch[114359296];

#define OFF_XLR0  0u
#define OFF_XLR1  25600000u
#define OFF_H     51200000u
#define OFF_H1    64000000u
#define OFF_P1    67200000u
#define OFF_P2    70400000u
#define OFF_XR    73600000u
#define OFF_WT    112000000u

// CSR structures (ints)
__device__ int g_rowptr[RN * (NN + 1)];
__device__ int g_colidx[RN * EE];
__device__ int g_tmp[2 * RN * NN];   // counts | cursor

// ===========================================================================
// PTX helpers (all plain-sm_103-legal: cp.async, ldmatrix, mma.sync)
// ===========================================================================
__device__ __forceinline__ uint32_t smem_u32(const void* p) {
    uint32_t a;
    asm("{ .reg .u64 t; cvta.to.shared.u64 t, %1; cvt.u32.u64 %0, t; }"
        : "=r"(a) : "l"(p));
    return a;
}
__device__ __forceinline__ void cp16(uint32_t dst, const void* src, uint32_t sz) {
    asm volatile("cp.async.cg.shared.global [%0], [%1], 16, %2;"
                 :: "r"(dst), "l"(src), "r"(sz) : "memory");
}
__device__ __forceinline__ void cp_commit() {
    asm volatile("cp.async.commit_group;" ::: "memory");
}
__device__ __forceinline__ void cp_wait2() {
    asm volatile("cp.async.wait_group 2;" ::: "memory");
}
#define LDSM4(r0, r1, r2, r3, addr) \
    asm volatile("ldmatrix.sync.aligned.m8n8.x4.shared.b16 {%0,%1,%2,%3}, [%4];" \
                 : "=r"(r0), "=r"(r1), "=r"(r2), "=r"(r3) : "r"(addr))

#define MMA_TF32(d, a, b0, b1) \
    asm volatile("mma.sync.aligned.m16n8k8.row.col.f32.tf32.tf32.f32 " \
                 "{%0,%1,%2,%3}, {%4,%5,%6,%7}, {%8,%9}, {%0,%1,%2,%3};" \
                 : "+f"((d)[0]), "+f"((d)[1]), "+f"((d)[2]), "+f"((d)[3]) \
                 : "r"((a)[0]), "r"((a)[1]), "r"((a)[2]), "r"((a)[3]), \
                   "r"(b0), "r"(b1))

// ===========================================================================
// Preprocessing: tf32 rounding + weight transpose
// ===========================================================================
__device__ __forceinline__ float rna_tf32(float v) {
    uint32_t o;
    asm("cvt.rna.tf32.f32 %0, %1;" : "=r"(o) : "f"(v));
    return __uint_as_float(o);
}

__global__ void round_tf32_kernel(const float4* __restrict__ in, float4* __restrict__ out, int n4) {
    int i = blockIdx.x * blockDim.x + threadIdx.x;
    int stride = gridDim.x * blockDim.x;
    for (; i < n4; i += stride) {
        float4 v = in[i];
        v.x = rna_tf32(v.x); v.y = rna_tf32(v.y);
        v.z = rna_tf32(v.z); v.w = rna_tf32(v.w);
        out[i] = v;
    }
}

// WT[r][n][k] = rna(Wl[r][k][n]) for n<256, rna(Wr[r][k][n-256]) otherwise
__global__ void transpose_w_kernel(const float* __restrict__ Wl, const float* __restrict__ Wr,
                                   float* __restrict__ WT) {
    __shared__ float tile[32][33];
    int r = blockIdx.z;
    int k0 = blockIdx.x * 32;
    int n0 = blockIdx.y * 32;
    const float* W = (n0 < 256) ? Wl : Wr;
    int nc0 = (n0 < 256) ? n0 : (n0 - 256);
    int tx = threadIdx.x, ty = threadIdx.y;  // 32 x 8
#pragma unroll
    for (int i = 0; i < 32; i += 8) {
        float v = W[((size_t)r * DD + k0 + ty + i) * HC + nc0 + tx];
        tile[ty + i][tx] = rna_tf32(v);
    }
    __syncthreads();
#pragma unroll
    for (int i = 0; i < 32; i += 8) {
        WT[((size_t)r * 512 + n0 + ty + i) * DD + k0 + tx] = tile[tx][ty + i];
    }
}

// ===========================================================================
// CSR build: zero -> histogram -> scan -> fill
// ===========================================================================
__global__ void zero_int_kernel(int* p, int n) {
    int i = blockIdx.x * blockDim.x + threadIdx.x;
    int stride = gridDim.x * blockDim.x;
    for (; i < n; i += stride) p[i] = 0;
}

__global__ void hist_kernel(const int* __restrict__ ei, int* __restrict__ counts) {
    int i = blockIdx.x * blockDim.x + threadIdx.x;
    if (i >= RN * EE) return;
    int r = i / EE, e = i - r * EE;
    int t = ei[(size_t)r * 2 * EE + EE + e];
    atomicAdd(&counts[r * NN + t], 1);
}

// one block per relation; chunked Hillis-Steele inclusive scan
__global__ void __launch_bounds__(1024)
scan_kernel(const int* __restrict__ counts, int* __restrict__ rowptr) {
    int r = blockIdx.x;
    const int* c = counts + r * NN;
    int* rp = rowptr + r * (NN + 1);
    __shared__ int sdata[1024];
    __shared__ int carry_s;
    if (threadIdx.x == 0) { carry_s = 0; rp[0] = 0; }
    __syncthreads();
    for (int base = 0; base < NN; base += 1024) {
        int i = base + threadIdx.x;
        int v = (i < NN) ? c[i] : 0;
        sdata[threadIdx.x] = v;
        __syncthreads();
#pragma unroll
        for (int off = 1; off < 1024; off <<= 1) {
            int tv = (threadIdx.x >= off) ? sdata[threadIdx.x - off] : 0;
            __syncthreads();
            sdata[threadIdx.x] += tv;
            __syncthreads();
        }
        int carry = carry_s;
        if (i < NN) rp[i + 1] = carry + sdata[threadIdx.x];
        __syncthreads();
        if (threadIdx.x == 1023) carry_s = carry + sdata[1023];
        __syncthreads();
    }
}

__global__ void fillcsr_kernel(const int* __restrict__ ei, const int* __restrict__ rowptr,
                               int* __restrict__ cursor, int* __restrict__ colidx) {
    int i = blockIdx.x * blockDim.x + threadIdx.x;
    if (i >= RN * EE) return;
    int r = i / EE, e = i - r * EE;
    int s = ei[(size_t)r * 2 * EE + e];
    int t = ei[(size_t)r * 2 * EE + EE + e];
    int pos = rowptr[r * (NN + 1) + t] + atomicAdd(&cursor[r * NN + t], 1);
    colidx[r * EE + pos] = s;
}

// ===========================================================================
// tf32 mma.sync GEMM: C[M][512] tile = A[M][768] @ B[512][768]^T
// BM=128 BN=128 BK=32, 4-stage cp.async, 8 warps, warp tile 64x32.
// ===========================================================================
#define BM 128
#define BN 128
#define BK 32
#define GSTG 4
#define KIT (DD / BK)               // 24
#define TILE_BYTES (BM * BK * 4)    // 16384
#define SMEM_GEMM (GSTG * 2 * TILE_BYTES + 1024)

__global__ void __launch_bounds__(256, 1)
gemm_xlr_mma_kernel(const float* __restrict__ A, const float* __restrict__ B,
                    float* __restrict__ C, int M) {
    extern __shared__ char sm_raw[];
    uint32_t smbase = (smem_u32(sm_raw) + 1023u) & ~1023u;
    uint32_t sA = smbase;
    uint32_t sB = smbase + GSTG * TILE_BYTES;

    int tid = threadIdx.x;
    int lane = tid & 31, wid = tid >> 5;
    int wm = wid & 1, wn = wid >> 1;
    int M0 = blockIdx.y * BM, N0 = blockIdx.x * BN;

    uint32_t dstOff[4];
    const float* srcA[4]; uint32_t szA[4];
    const float* srcB[4];
#pragma unroll
    for (int i = 0; i < 4; i++) {
        int lin = tid + i * 256;
        int row = lin >> 3, ch = lin & 7;
        dstOff[i] = row * 128 + ((ch * 16) ^ ((row & 7) * 16));
        int ga = M0 + row;
        szA[i] = (ga < M) ? 16u : 0u;
        srcA[i] = A + (size_t)(ga < M ? ga : 0) * DD + ch * 4;
        srcB[i] = B + (size_t)(N0 + row) * DD + ch * 4;
    }

    uint32_t aOff[4], bOff[2];
#pragma unroll
    for (int mt = 0; mt < 4; mt++) {
        int rowA = wm * 64 + mt * 16 + (lane & 7) + ((lane >> 3) & 1) * 8;
        uint32_t q = (uint32_t)(((lane >> 4) * 16) ^ ((rowA & 7) * 16));
        aOff[mt] = (uint32_t)rowA * 128 + q;
    }
#pragma unroll
    for (int bp = 0; bp < 2; bp++) {
        int rowB = wn * 32 + bp * 16 + (lane & 7) + ((lane >> 4) & 1) * 8;
        uint32_t q = (uint32_t)((((lane >> 3) & 1) * 16) ^ ((rowB & 7) * 16));
        bOff[bp] = (uint32_t)rowB * 128 + q;
    }

    float acc[4][4][4];
#pragma unroll
    for (int mt = 0; mt < 4; mt++)
#pragma unroll
        for (int nt = 0; nt < 4; nt++)
#pragma unroll
            for (int j = 0; j < 4; j++) acc[mt][nt][j] = 0.f;

#pragma unroll
    for (int s = 0; s < 3; s++) {
#pragma unroll
        for (int i = 0; i < 4; i++) {
            cp16(sA + s * TILE_BYTES + dstOff[i], srcA[i] + s * BK, szA[i]);
            cp16(sB + s * TILE_BYTES + dstOff[i], srcB[i] + s * BK, 16u);
        }
        cp_commit();
    }

    for (int it = 0; it < KIT; it++) {
        cp_wait2();
        __syncthreads();

        int nx = it + 3;
        if (nx < KIT) {
            int s2 = nx % GSTG;
#pragma unroll
            for (int i = 0; i < 4; i++) {
                cp16(sA + s2 * TILE_BYTES + dstOff[i], srcA[i] + nx * BK, szA[i]);
                cp16(sB + s2 * TILE_BYTES + dstOff[i], srcB[i] + nx * BK, 16u);
            }
        }
        cp_commit();

        int s = it % GSTG;
        uint32_t baseA = sA + s * TILE_BYTES;
        uint32_t baseB = sB + s * TILE_BYTES;
#pragma unroll
        for (int ks = 0; ks < 4; ks++) {
            uint32_t afr[4][4];
            uint32_t bfr[4][2];
#pragma unroll
            for (int mt = 0; mt < 4; mt++)
                LDSM4(afr[mt][0], afr[mt][1], afr[mt][2], afr[mt][3],
                      baseA + (aOff[mt] ^ (uint32_t)(ks * 32)));
#pragma unroll
            for (int bp = 0; bp < 2; bp++) {
                uint32_t r0, r1, r2, r3;
                LDSM4(r0, r1, r2, r3, baseB + (bOff[bp] ^ (uint32_t)(ks * 32)));
                bfr[2 * bp][0] = r0;     bfr[2 * bp][1] = r1;
                bfr[2 * bp + 1][0] = r2; bfr[2 * bp + 1][1] = r3;
            }
#pragma unroll
            for (int mt = 0; mt < 4; mt++)
#pragma unroll
                for (int nt = 0; nt < 4; nt++)
                    MMA_TF32(acc[mt][nt], afr[mt], bfr[nt][0], bfr[nt][1]);
        }
    }

    int r = lane >> 2, c = (lane & 3) * 2;
#pragma unroll
    for (int mt = 0; mt < 4; mt++) {
        int grow = M0 + wm * 64 + mt * 16 + r;
#pragma unroll
        for (int nt = 0; nt < 4; nt++) {
            int gcol = N0 + wn * 32 + nt * 8 + c;
            if (grow < M)
                *(float2*)(C + (size_t)grow * 512 + gcol) =
                    make_float2(acc[mt][nt][0], acc[mt][nt][1]);
            if (grow + 8 < M)
                *(float2*)(C + (size_t)(grow + 8) * 512 + gcol) =
                    make_float2(acc[mt][nt][2], acc[mt][nt][3]);
        }
    }
}

// ===========================================================================
// GATv2 CSR pass: warp per target node. Gathers xl[s] for incoming edges
// (+self-loop), accumulates unnormalized messages + denom in registers,
// writes h[t] = relu(acc/denom + bias) directly. NO atomics, NO zero-fill.
// Lane owns 8 contiguous channels (head = lane>>3); butterfly over the
// 8-lane group yields the head logit in every lane.
// ===========================================================================
__global__ void gat_csr_kernel(const float* __restrict__ XLR,
                               const int* __restrict__ rowptr, const int* __restrict__ colidx,
                               const float* __restrict__ att, const float* __restrict__ bias,
                               float* __restrict__ h) {
    int warp = (blockIdx.x * blockDim.x + threadIdx.x) >> 5;
    int lane = threadIdx.x & 31;
    if (warp >= NN) return;
    int t = warp;
    int base = lane * 8;

    float4 a0 = *(const float4*)(att + base), a1 = *(const float4*)(att + base + 4);
    const float* xrp = XLR + (size_t)t * 512 + 256 + base;
    float4 r0 = *(const float4*)xrp, r1 = *(const float4*)(xrp + 4);

    float acc0 = 0.f, acc1 = 0.f, acc2 = 0.f, acc3 = 0.f;
    float acc4 = 0.f, acc5 = 0.f, acc6 = 0.f, acc7 = 0.f;
    float denom = 0.f;

    int beg = rowptr[t], end = rowptr[t + 1];
    for (int j = beg; j <= end; j++) {       // j == end -> self-loop
        int s = (j < end) ? colidx[j] : t;
        const float* xlp = XLR + (size_t)s * 512 + base;
        float4 l0 = *(const float4*)xlp, l1 = *(const float4*)(xlp + 4);
#define LRELU(v) ((v) > 0.f ? (v) : 0.2f * (v))
        float sum = LRELU(l0.x + r0.x) * a0.x + LRELU(l0.y + r0.y) * a0.y
                  + LRELU(l0.z + r0.z) * a0.z + LRELU(l0.w + r0.w) * a0.w
                  + LRELU(l1.x + r1.x) * a1.x + LRELU(l1.y + r1.y) * a1.y
                  + LRELU(l1.z + r1.z) * a1.z + LRELU(l1.w + r1.w) * a1.w;
#undef LRELU
        sum += __shfl_xor_sync(0xffffffffu, sum, 1);
        sum += __shfl_xor_sync(0xffffffffu, sum, 2);
        sum += __shfl_xor_sync(0xffffffffu, sum, 4);
        float e = expf(sum);
        acc0 += e * l0.x; acc1 += e * l0.y; acc2 += e * l0.z; acc3 += e * l0.w;
        acc4 += e * l1.x; acc5 += e * l1.y; acc6 += e * l1.z; acc7 += e * l1.w;
        denom += e;
    }

    float rd = __frcp_rn(denom + 1e-16f);
    float4 b0v = *(const float4*)(bias + base), b1v = *(const float4*)(bias + base + 4);
    float4 o0 = make_float4(fmaxf(acc0 * rd + b0v.x, 0.f), fmaxf(acc1 * rd + b0v.y, 0.f),
                            fmaxf(acc2 * rd + b0v.z, 0.f), fmaxf(acc3 * rd + b0v.w, 0.f));
    float4 o1 = make_float4(fmaxf(acc4 * rd + b1v.x, 0.f), fmaxf(acc5 * rd + b1v.y, 0.f),
                            fmaxf(acc6 * rd + b1v.z, 0.f), fmaxf(acc7 * rd + b1v.w, 0.f));
    float* hp = h + (size_t)t * 256 + base;
    *(float4*)hp = o0;
    *(float4*)(hp + 4) = o1;
}

// ===========================================================================
// CSR gather (64-wide): dst[t] += sum_{s in CSR(t)} p[s]; optional relu.
// Warp per target; lane owns 2 floats. dst pre-seeded with root+bias by GEMM.
// ===========================================================================
__global__ void gather_csr64_kernel(const float* __restrict__ p,
                                    const int* __restrict__ rowptr, const int* __restrict__ colidx,
                                    float* __restrict__ dst, int ldd, int relu) {
    int warp = (blockIdx.x * blockDim.x + threadIdx.x) >> 5;
    int lane = threadIdx.x & 31;
    if (warp >= NN) return;
    int t = warp;
    float* dp = dst + (size_t)t * ldd + lane * 2;
    float2 acc = *(float2*)dp;
    int beg = rowptr[t], end = rowptr[t + 1];
    for (int j = beg; j < end; j++) {
        int s = colidx[j];
        float2 v = *(const float2*)(p + (size_t)s * 64 + lane * 2);
        acc.x += v.x; acc.y += v.y;
    }
    if (relu) { acc.x = fmaxf(acc.x, 0.f); acc.y = fmaxf(acc.y, 0.f); }
    *(float2*)dp = acc;
}

// ===========================================================================
// Dual small GEMM: C1 = A@B1 (ldc 64); C2 = A@B2 + bias (ldc param)
// ===========================================================================
__global__ void __launch_bounds__(256)
gemm64_dual_kernel(const float* __restrict__ A,
                   const float* __restrict__ B1, const float* __restrict__ B2,
                   const float* __restrict__ bias,
                   float* __restrict__ C1, float* __restrict__ C2,
                   int ldc2, int M, int K) {
    __shared__ float As[32][68];
    __shared__ float B1s[32][64];
    __shared__ float B2s[32][64];
    int m0 = blockIdx.x * 64;
    int tid = threadIdx.x;
    int tx = tid & 15, ty = tid >> 4;
    float acc1[4][4], acc2[4][4];
#pragma unroll
    for (int i = 0; i < 4; i++)
#pragma unroll
        for (int j = 0; j < 4; j++) { acc1[i][j] = 0.f; acc2[i][j] = 0.f; }

    for (int k0 = 0; k0 < K; k0 += 32) {
#pragma unroll
        for (int l = 0; l < 2; l++) {
            int lin = tid + l * 256;
            int row = lin >> 3, kc = (lin & 7) * 4;
            float4 v = make_float4(0.f, 0.f, 0.f, 0.f);
            int gm = m0 + row;
            if (gm < M) v = *(const float4*)(A + (size_t)gm * K + k0 + kc);
            As[kc + 0][row] = v.x; As[kc + 1][row] = v.y;
            As[kc + 2][row] = v.z; As[kc + 3][row] = v.w;

            int br = lin >> 4, bc = (lin & 15) * 4;
            *(float4*)&B1s[br][bc] = *(const float4*)(B1 + (size_t)(k0 + br) * 64 + bc);
            *(float4*)&B2s[br][bc] = *(const float4*)(B2 + (size_t)(k0 + br) * 64 + bc);
        }
        __syncthreads();
#pragma unroll
        for (int k = 0; k < 32; k++) {
            float a[4], b1v[4], b2v[4];
#pragma unroll
            for (int i = 0; i < 4; i++) a[i] = As[k][ty * 4 + i];
#pragma unroll
            for (int j = 0; j < 4; j++) { b1v[j] = B1s[k][tx * 4 + j]; b2v[j] = B2s[k][tx * 4 + j]; }
#pragma unroll
            for (int i = 0; i < 4; i++)
#pragma unroll
                for (int j = 0; j < 4; j++) {
                    acc1[i][j] += a[i] * b1v[j];
                    acc2[i][j] += a[i] * b2v[j];
                }
        }
        __syncthreads();
    }

    float bj[4];
#pragma unroll
    for (int j = 0; j < 4; j++) bj[j] = bias[tx * 4 + j];
#pragma unroll
    for (int i = 0; i < 4; i++) {
        int gm = m0 + ty * 4 + i;
        if (gm < M) {
            *(float4*)(C1 + (size_t)gm * 64 + tx * 4) =
                make_float4(acc1[i][0], acc1[i][1], acc1[i][2], acc1[i][3]);
            *(float4*)(C2 + (size_t)gm * ldc2 + tx * 4) =
                make_float4(acc2[i][0] + bj[0], acc2[i][1] + bj[1],
                            acc2[i][2] + bj[2], acc2[i][3] + bj[3]);
        }
    }
}

// ===========================================================================
// Host launch: CSR build once, then fork-join two streams under capture.
// ===========================================================================
extern "C" void kernel_launch(void* const* d_in, const int* in_sizes, int n_in,
                              void* d_out, int out_size) {
    const float* x      = (const float*)d_in[0];
    const int*   ei     = (const int*)  d_in[1];   // [R,2,E]
    const float* Wl     = (const float*)d_in[2];   // [R,768,256]
    const float* Wr     = (const float*)d_in[3];
    const float* att    = (const float*)d_in[4];   // [R,4,64]
    const float* bg     = (const float*)d_in[5];   // [R,256]
    const float* Wrel1  = (const float*)d_in[6];   // [R,256,64]
    const float* Wroot1 = (const float*)d_in[7];
    const float* b1     = (const float*)d_in[8];   // [R,64]
    const float* Wrel2  = (const float*)d_in[9];   // [R,64,64]
    const float* Wroot2 = (const float*)d_in[10];
    const float* b2     = (const float*)d_in[11];  // [R,64]
    float* out = (float*)d_out;                    // [N,R,64]

    float* scratch = nullptr;
    cudaGetSymbolAddress((void**)&scratch, g_scratch);
    float* XLRbuf[2] = { scratch + OFF_XLR0, scratch + OFF_XLR1 };
    float* h   = scratch + OFF_H;
    float* h1  = scratch + OFF_H1;
    float* p1  = scratch + OFF_P1;
    float* p2  = scratch + OFF_P2;
    float* XR  = scratch + OFF_XR;
    float* WT  = scratch + OFF_WT;

    int *rowptr = nullptr, *colidx = nullptr, *tmp = nullptr;
    cudaGetSymbolAddress((void**)&rowptr, g_rowptr);
    cudaGetSymbolAddress((void**)&colidx, g_colidx);
    cudaGetSymbolAddress((void**)&tmp, g_tmp);
    int* counts = tmp;
    int* cursor = tmp + RN * NN;

    // One-time host-side resources.
    static cudaStream_t sG = nullptr;
    static cudaEvent_t evPre, evG[RN], evFree[RN];
    if (!sG) {
        cudaStreamCreateWithFlags(&sG, cudaStreamNonBlocking);
        cudaEventCreateWithFlags(&evPre, cudaEventDisableTiming);
        for (int r = 0; r < RN; r++) {
            cudaEventCreateWithFlags(&evG[r], cudaEventDisableTiming);
            cudaEventCreateWithFlags(&evFree[r], cudaEventDisableTiming);
        }
        cudaFuncSetAttribute(gemm_xlr_mma_kernel,
                             cudaFuncAttributeMaxDynamicSharedMemorySize, SMEM_GEMM);
    }

    const int M = NN;
    int nodeBlocks = (NN * 32 + 255) / 256;   // warp per node
    cudaStream_t sM = 0;  // main (capture-origin) stream

    // --- preprocessing (main stream) ---
    round_tf32_kernel<<<4096, 256, 0, sM>>>((const float4*)x, (float4*)XR, NN * DD / 4);
    transpose_w_kernel<<<dim3(24, 16, RN), dim3(32, 8), 0, sM>>>(Wl, Wr, WT);
    // CSR build (all relations)
    zero_int_kernel<<<1024, 256, 0, sM>>>(tmp, 2 * RN * NN);
    hist_kernel<<<(RN * EE + 255) / 256, 256, 0, sM>>>(ei, counts);
    scan_kernel<<<RN, 1024, 0, sM>>>(counts, rowptr);
    fillcsr_kernel<<<(RN * EE + 255) / 256, 256, 0, sM>>>(ei, rowptr, cursor, colidx);

    cudaEventRecord(evPre, sM);
    cudaStreamWaitEvent(sG, evPre, 0);

    for (int r = 0; r < RN; r++) {
        const int* rp = rowptr + r * (NN + 1);
        const int* ci = colidx + r * EE;
        float* XLR = XLRbuf[r & 1];

        // --- side stream: big GEMM for relation r ---
        if (r >= 2) cudaStreamWaitEvent(sG, evFree[r - 2], 0);
        gemm_xlr_mma_kernel<<<dim3(4, (M + BM - 1) / BM), 256, SMEM_GEMM, sG>>>(
            XR, WT + (size_t)r * 512 * DD, XLR, M);
        cudaEventRecord(evG[r], sG);

        // --- main stream: relation r pipeline ---
        cudaStreamWaitEvent(sM, evG[r], 0);

        // GATv2: CSR gather, fully fused (normalize + bias + relu)
        gat_csr_kernel<<<nodeBlocks, 256, 0, sM>>>(XLR, rp, ci,
                                                   att + (size_t)r * HC,
                                                   bg + (size_t)r * HC, h);
        cudaEventRecord(evFree[r], sM);  // last reader of XLRbuf[r&1]

        // GraphConv 1: h1 = relu( gather(p1) + h@Wroot1 + b1 ), p1 = h@Wrel1
        gemm64_dual_kernel<<<(M + 63) / 64, 256, 0, sM>>>(
            h, Wrel1 + (size_t)r * HC * OO, Wroot1 + (size_t)r * HC * OO,
            b1 + (size_t)r * OO, p1, h1, OO, M, HC);
        gather_csr64_kernel<<<nodeBlocks, 256, 0, sM>>>(p1, rp, ci, h1, OO, 1);

        // GraphConv 2 -> out[:, r, :]
        gemm64_dual_kernel<<<(M + 63) / 64, 256, 0, sM>>>(
            h1, Wrel2 + (size_t)r * OO * OO, Wroot2 + (size_t)r * OO * OO,
            b2 + (size_t)r * OO, p2, out + (size_t)r * OO, RN * OO, M, OO);
        gather_csr64_kernel<<<nodeBlocks, 256, 0, sM>>>(p2, rp, ci,
                                                        out + (size_t)r * OO, RN * OO, 0);
    }
}

// round 7
// speedup vs baseline: 3.4112x; 1.1526x over previous
#include <cuda_runtime.h>
#include <cstdint>
#include <cstddef>

// Problem constants (fixed by the reference)
#define RN 6
#define NN 50000
#define EE 200000
#define DD 768
#define HC 256      // H*C
#define OO 64

// ---------------------------------------------------------------------------
// Scratch layout (floats)
//   XLR0 : [N][512]    xl|xr buffer 0                          25,600,000
//   XLR1 : [N][512]    xl|xr buffer 1                          25,600,000
//   h    : [N][256]    GAT output (relu'd, tf32-rounded)       12,800,000
//   h1   : [N][64]                                              3,200,000
//   p1   : [N][64]                                              3,200,000
//   p2   : [N][64]                                              3,200,000
//   XR   : [N][768]    tf32-rounded x                          38,400,000
//   WT   : [R][512][768]  tf32 [Wl|Wr]^T                        2,359,296
//   WB1  : [R][128][256]  tf32 [Wrel1|Wroot1]^T                   196,608
// ---------------------------------------------------------------------------
__device__ float g_scratch[114555904];

#define OFF_XLR0  0u
#define OFF_XLR1  25600000u
#define OFF_H     51200000u
#define OFF_H1    64000000u
#define OFF_P1    67200000u
#define OFF_P2    70400000u
#define OFF_XR    73600000u
#define OFF_WT    112000000u
#define OFF_WB1   114359296u

// CSR structures (ints)
__device__ int g_rowptr[RN * (NN + 1)];
__device__ int g_colidx[RN * EE];
__device__ int g_tmp[2 * RN * NN];   // counts | cursor

// ===========================================================================
// PTX helpers (plain-sm_103-legal: cp.async, ldmatrix, mma.sync)
// ===========================================================================
__device__ __forceinline__ uint32_t smem_u32(const void* p) {
    uint32_t a;
    asm("{ .reg .u64 t; cvta.to.shared.u64 t, %1; cvt.u32.u64 %0, t; }"
        : "=r"(a) : "l"(p));
    return a;
}
__device__ __forceinline__ void cp16(uint32_t dst, const void* src, uint32_t sz) {
    asm volatile("cp.async.cg.shared.global [%0], [%1], 16, %2;"
                 :: "r"(dst), "l"(src), "r"(sz) : "memory");
}
__device__ __forceinline__ void cp_commit() {
    asm volatile("cp.async.commit_group;" ::: "memory");
}
__device__ __forceinline__ void cp_wait2() {
    asm volatile("cp.async.wait_group 2;" ::: "memory");
}
#define LDSM4(r0, r1, r2, r3, addr) \
    asm volatile("ldmatrix.sync.aligned.m8n8.x4.shared.b16 {%0,%1,%2,%3}, [%4];" \
                 : "=r"(r0), "=r"(r1), "=r"(r2), "=r"(r3) : "r"(addr))

#define MMA_TF32(d, a, b0, b1) \
    asm volatile("mma.sync.aligned.m16n8k8.row.col.f32.tf32.tf32.f32 " \
                 "{%0,%1,%2,%3}, {%4,%5,%6,%7}, {%8,%9}, {%0,%1,%2,%3};" \
                 : "+f"((d)[0]), "+f"((d)[1]), "+f"((d)[2]), "+f"((d)[3]) \
                 : "r"((a)[0]), "r"((a)[1]), "r"((a)[2]), "r"((a)[3]), \
                   "r"(b0), "r"(b1))

// ===========================================================================
// Preprocessing: tf32 rounding + weight transposes
// ===========================================================================
__device__ __forceinline__ float rna_tf32(float v) {
    uint32_t o;
    asm("cvt.rna.tf32.f32 %0, %1;" : "=r"(o) : "f"(v));
    return __uint_as_float(o);
}

__global__ void round_tf32_kernel(const float4* __restrict__ in, float4* __restrict__ out, int n4) {
    int i = blockIdx.x * blockDim.x + threadIdx.x;
    int stride = gridDim.x * blockDim.x;
    for (; i < n4; i += stride) {
        float4 v = in[i];
        v.x = rna_tf32(v.x); v.y = rna_tf32(v.y);
        v.z = rna_tf32(v.z); v.w = rna_tf32(v.w);
        out[i] = v;
    }
}

// WT[r][n][k] = rna(Wl[r][k][n]) for n<256 else rna(Wr[r][k][n-256])
__global__ void transpose_w_kernel(const float* __restrict__ Wl, const float* __restrict__ Wr,
                                   float* __restrict__ WT) {
    __shared__ float tile[32][33];
    int r = blockIdx.z;
    int k0 = blockIdx.x * 32;
    int n0 = blockIdx.y * 32;
    const float* W = (n0 < 256) ? Wl : Wr;
    int nc0 = (n0 < 256) ? n0 : (n0 - 256);
    int tx = threadIdx.x, ty = threadIdx.y;  // 32 x 8
#pragma unroll
    for (int i = 0; i < 32; i += 8) {
        float v = W[((size_t)r * DD + k0 + ty + i) * HC + nc0 + tx];
        tile[ty + i][tx] = rna_tf32(v);
    }
    __syncthreads();
#pragma unroll
    for (int i = 0; i < 32; i += 8) {
        WT[((size_t)r * 512 + n0 + ty + i) * DD + k0 + tx] = tile[tx][ty + i];
    }
}

// WB1[r][n][k] = rna(Wrel1[r][k][n]) for n<64 else rna(Wroot1[r][k][n-64]); K=256
__global__ void transpose_wb1_kernel(const float* __restrict__ Wrel1,
                                     const float* __restrict__ Wroot1,
                                     float* __restrict__ WB1) {
    __shared__ float tile[32][33];
    int r = blockIdx.z;
    int k0 = blockIdx.x * 32;   // 8 blocks (K=256)
    int n0 = blockIdx.y * 32;   // 4 blocks (N=128)
    const float* W = (n0 < 64) ? Wrel1 : Wroot1;
    int nc0 = (n0 < 64) ? n0 : (n0 - 64);
    int tx = threadIdx.x, ty = threadIdx.y;  // 32 x 8
#pragma unroll
    for (int i = 0; i < 32; i += 8) {
        float v = W[((size_t)r * HC + k0 + ty + i) * OO + nc0 + tx];
        tile[ty + i][tx] = rna_tf32(v);
    }
    __syncthreads();
#pragma unroll
    for (int i = 0; i < 32; i += 8) {
        WB1[((size_t)r * 128 + n0 + ty + i) * HC + k0 + tx] = tile[tx][ty + i];
    }
}

// ===========================================================================
// CSR build: zero -> histogram -> scan -> fill
// ===========================================================================
__global__ void zero_int_kernel(int* p, int n) {
    int i = blockIdx.x * blockDim.x + threadIdx.x;
    int stride = gridDim.x * blockDim.x;
    for (; i < n; i += stride) p[i] = 0;
}

__global__ void hist_kernel(const int* __restrict__ ei, int* __restrict__ counts) {
    int i = blockIdx.x * blockDim.x + threadIdx.x;
    if (i >= RN * EE) return;
    int r = i / EE, e = i - r * EE;
    int t = ei[(size_t)r * 2 * EE + EE + e];
    atomicAdd(&counts[r * NN + t], 1);
}

__global__ void __launch_bounds__(1024)
scan_kernel(const int* __restrict__ counts, int* __restrict__ rowptr) {
    int r = blockIdx.x;
    const int* c = counts + r * NN;
    int* rp = rowptr + r * (NN + 1);
    __shared__ int sdata[1024];
    __shared__ int carry_s;
    if (threadIdx.x == 0) { carry_s = 0; rp[0] = 0; }
    __syncthreads();
    for (int base = 0; base < NN; base += 1024) {
        int i = base + threadIdx.x;
        int v = (i < NN) ? c[i] : 0;
        sdata[threadIdx.x] = v;
        __syncthreads();
#pragma unroll
        for (int off = 1; off < 1024; off <<= 1) {
            int tv = (threadIdx.x >= off) ? sdata[threadIdx.x - off] : 0;
            __syncthreads();
            sdata[threadIdx.x] += tv;
            __syncthreads();
        }
        int carry = carry_s;
        if (i < NN) rp[i + 1] = carry + sdata[threadIdx.x];
        __syncthreads();
        if (threadIdx.x == 1023) carry_s = carry + sdata[1023];
        __syncthreads();
    }
}

__global__ void fillcsr_kernel(const int* __restrict__ ei, const int* __restrict__ rowptr,
                               int* __restrict__ cursor, int* __restrict__ colidx) {
    int i = blockIdx.x * blockDim.x + threadIdx.x;
    if (i >= RN * EE) return;
    int r = i / EE, e = i - r * EE;
    int s = ei[(size_t)r * 2 * EE + e];
    int t = ei[(size_t)r * 2 * EE + EE + e];
    int pos = rowptr[r * (NN + 1) + t] + atomicAdd(&cursor[r * NN + t], 1);
    colidx[r * EE + pos] = s;
}

// ===========================================================================
// Templated tf32 mma.sync GEMM.
//   non-DUAL: C[M][ldc] tile (BMxBN) = A[M][K] @ B[Nrows][K]^T, grid.x tiles N
//   DUAL:     N=128 fixed, cols 0..63 -> C (ldc 64), cols 64..127 -> C2+bias
// BM=128 BN=128 BK=32, 4-stage cp.async, 8 warps (2m x 4n), warp tile 64x32,
// ks-prefetched (double-buffered) ldmatrix fragments.
// ===========================================================================
#define BM 128
#define BN 128
#define BK 32
#define GSTG 4
#define TILE_BYTES (BM * BK * 4)    // 16384
#define SMEM_GEMM (GSTG * 2 * TILE_BYTES + 1024)

template<int KITN, bool DUAL>
__global__ void __launch_bounds__(256, 1)
gemm_mma_kernel(const float* __restrict__ A, const float* __restrict__ B,
                float* __restrict__ C, float* __restrict__ C2,
                const float* __restrict__ bias, int ldc, int M, int K) {
    extern __shared__ char sm_raw[];
    uint32_t smbase = (smem_u32(sm_raw) + 1023u) & ~1023u;
    uint32_t sA = smbase;
    uint32_t sB = smbase + GSTG * TILE_BYTES;

    int tid = threadIdx.x;
    int lane = tid & 31, wid = tid >> 5;
    int wm = wid & 1, wn = wid >> 1;
    int M0 = blockIdx.y * BM, N0 = blockIdx.x * BN;

    uint32_t dstOff[4];
    const float* srcA[4]; uint32_t szA[4];
    const float* srcB[4];
#pragma unroll
    for (int i = 0; i < 4; i++) {
        int lin = tid + i * 256;
        int row = lin >> 3, ch = lin & 7;
        dstOff[i] = row * 128 + ((ch * 16) ^ ((row & 7) * 16));
        int ga = M0 + row;
        szA[i] = (ga < M) ? 16u : 0u;
        srcA[i] = A + (size_t)(ga < M ? ga : 0) * K + ch * 4;
        srcB[i] = B + (size_t)(N0 + row) * K + ch * 4;
    }

    uint32_t aOff[4], bOff[2];
#pragma unroll
    for (int mt = 0; mt < 4; mt++) {
        int rowA = wm * 64 + mt * 16 + (lane & 7) + ((lane >> 3) & 1) * 8;
        uint32_t q = (uint32_t)(((lane >> 4) * 16) ^ ((rowA & 7) * 16));
        aOff[mt] = (uint32_t)rowA * 128 + q;
    }
#pragma unroll
    for (int bp = 0; bp < 2; bp++) {
        int rowB = wn * 32 + bp * 16 + (lane & 7) + ((lane >> 4) & 1) * 8;
        uint32_t q = (uint32_t)((((lane >> 3) & 1) * 16) ^ ((rowB & 7) * 16));
        bOff[bp] = (uint32_t)rowB * 128 + q;
    }

    float acc[4][4][4];
#pragma unroll
    for (int mt = 0; mt < 4; mt++)
#pragma unroll
        for (int nt = 0; nt < 4; nt++)
#pragma unroll
            for (int j = 0; j < 4; j++) acc[mt][nt][j] = 0.f;

    // prologue: stages 0..2
#pragma unroll
    for (int s = 0; s < 3; s++) {
#pragma unroll
        for (int i = 0; i < 4; i++) {
            cp16(sA + s * TILE_BYTES + dstOff[i], srcA[i] + s * BK, szA[i]);
            cp16(sB + s * TILE_BYTES + dstOff[i], srcB[i] + s * BK, 16u);
        }
        cp_commit();
    }

    uint32_t afr[2][4][4];
    uint32_t bfr[2][4][2];

    for (int it = 0; it < KITN; it++) {
        cp_wait2();
        __syncthreads();

        int nx = it + 3;
        if (nx < KITN) {
            int s2 = nx % GSTG;
#pragma unroll
            for (int i = 0; i < 4; i++) {
                cp16(sA + s2 * TILE_BYTES + dstOff[i], srcA[i] + nx * BK, szA[i]);
                cp16(sB + s2 * TILE_BYTES + dstOff[i], srcB[i] + nx * BK, 16u);
            }
        }
        cp_commit();

        int s = it % GSTG;
        uint32_t baseA = sA + s * TILE_BYTES;
        uint32_t baseB = sB + s * TILE_BYTES;

        // prefetch fragments for ks = 0 into buffer 0
#pragma unroll
        for (int mt = 0; mt < 4; mt++)
            LDSM4(afr[0][mt][0], afr[0][mt][1], afr[0][mt][2], afr[0][mt][3],
                  baseA + aOff[mt]);
#pragma unroll
        for (int bp = 0; bp < 2; bp++) {
            uint32_t r0, r1, r2, r3;
            LDSM4(r0, r1, r2, r3, baseB + bOff[bp]);
            bfr[0][2 * bp][0] = r0;     bfr[0][2 * bp][1] = r1;
            bfr[0][2 * bp + 1][0] = r2; bfr[0][2 * bp + 1][1] = r3;
        }

#pragma unroll
        for (int ks = 0; ks < 4; ks++) {
            int cur = ks & 1;
            if (ks < 3) {
                int nb = cur ^ 1;
                uint32_t x = (uint32_t)((ks + 1) * 32);
#pragma unroll
                for (int mt = 0; mt < 4; mt++)
                    LDSM4(afr[nb][mt][0], afr[nb][mt][1], afr[nb][mt][2], afr[nb][mt][3],
                          baseA + (aOff[mt] ^ x));
#pragma unroll
                for (int bp = 0; bp < 2; bp++) {
                    uint32_t r0, r1, r2, r3;
                    LDSM4(r0, r1, r2, r3, baseB + (bOff[bp] ^ x));
                    bfr[nb][2 * bp][0] = r0;     bfr[nb][2 * bp][1] = r1;
                    bfr[nb][2 * bp + 1][0] = r2; bfr[nb][2 * bp + 1][1] = r3;
                }
            }
#pragma unroll
            for (int mt = 0; mt < 4; mt++)
#pragma unroll
                for (int nt = 0; nt < 4; nt++)
                    MMA_TF32(acc[mt][nt], afr[cur][mt], bfr[cur][nt][0], bfr[cur][nt][1]);
        }
    }

    // epilogue
    int r = lane >> 2, c = (lane & 3) * 2;
#pragma unroll
    for (int mt = 0; mt < 4; mt++) {
        int grow = M0 + wm * 64 + mt * 16 + r;
#pragma unroll
        for (int nt = 0; nt < 4; nt++) {
            int gcol = wn * 32 + nt * 8 + c;
            float2 v01 = make_float2(acc[mt][nt][0], acc[mt][nt][1]);
            float2 v23 = make_float2(acc[mt][nt][2], acc[mt][nt][3]);
            if (DUAL) {
                if (gcol < 64) {
                    if (grow < M)     *(float2*)(C + (size_t)grow * 64 + gcol) = v01;
                    if (grow + 8 < M) *(float2*)(C + (size_t)(grow + 8) * 64 + gcol) = v23;
                } else {
                    float bx = bias[gcol - 64], by = bias[gcol - 63];
                    v01.x += bx; v01.y += by;
                    v23.x += bx; v23.y += by;
                    if (grow < M)     *(float2*)(C2 + (size_t)grow * 64 + gcol - 64) = v01;
                    if (grow + 8 < M) *(float2*)(C2 + (size_t)(grow + 8) * 64 + gcol - 64) = v23;
                }
            } else {
                if (grow < M)
                    *(float2*)(C + (size_t)grow * ldc + N0 + gcol) = v01;
                if (grow + 8 < M)
                    *(float2*)(C + (size_t)(grow + 8) * ldc + N0 + gcol) = v23;
            }
        }
    }
}

// ===========================================================================
// GATv2 CSR pass: warp per target node. h[t] = relu(acc/denom + bias),
// tf32-rounded so it can feed the tensor-core GraphConv-1 GEMM.
// ===========================================================================
__global__ void gat_csr_kernel(const float* __restrict__ XLR,
                               const int* __restrict__ rowptr, const int* __restrict__ colidx,
                               const float* __restrict__ att, const float* __restrict__ bias,
                               float* __restrict__ h) {
    int warp = (blockIdx.x * blockDim.x + threadIdx.x) >> 5;
    int lane = threadIdx.x & 31;
    if (warp >= NN) return;
    int t = warp;
    int base = lane * 8;

    float4 a0 = *(const float4*)(att + base), a1 = *(const float4*)(att + base + 4);
    const float* xrp = XLR + (size_t)t * 512 + 256 + base;
    float4 r0 = *(const float4*)xrp, r1 = *(const float4*)(xrp + 4);

    float acc0 = 0.f, acc1 = 0.f, acc2 = 0.f, acc3 = 0.f;
    float acc4 = 0.f, acc5 = 0.f, acc6 = 0.f, acc7 = 0.f;
    float denom = 0.f;

    int beg = rowptr[t], end = rowptr[t + 1];
    for (int j = beg; j <= end; j++) {       // j == end -> self-loop
        int s = (j < end) ? colidx[j] : t;
        const float* xlp = XLR + (size_t)s * 512 + base;
        float4 l0 = *(const float4*)xlp, l1 = *(const float4*)(xlp + 4);
#define LRELU(v) ((v) > 0.f ? (v) : 0.2f * (v))
        float sum = LRELU(l0.x + r0.x) * a0.x + LRELU(l0.y + r0.y) * a0.y
                  + LRELU(l0.z + r0.z) * a0.z + LRELU(l0.w + r0.w) * a0.w
                  + LRELU(l1.x + r1.x) * a1.x + LRELU(l1.y + r1.y) * a1.y
                  + LRELU(l1.z + r1.z) * a1.z + LRELU(l1.w + r1.w) * a1.w;
#undef LRELU
        sum += __shfl_xor_sync(0xffffffffu, sum, 1);
        sum += __shfl_xor_sync(0xffffffffu, sum, 2);
        sum += __shfl_xor_sync(0xffffffffu, sum, 4);
        float e = expf(sum);
        acc0 += e * l0.x; acc1 += e * l0.y; acc2 += e * l0.z; acc3 += e * l0.w;
        acc4 += e * l1.x; acc5 += e * l1.y; acc6 += e * l1.z; acc7 += e * l1.w;
        denom += e;
    }

    float rd = __frcp_rn(denom + 1e-16f);
    float4 b0v = *(const float4*)(bias + base), b1v = *(const float4*)(bias + base + 4);
    float4 o0 = make_float4(rna_tf32(fmaxf(acc0 * rd + b0v.x, 0.f)),
                            rna_tf32(fmaxf(acc1 * rd + b0v.y, 0.f)),
                            rna_tf32(fmaxf(acc2 * rd + b0v.z, 0.f)),
                            rna_tf32(fmaxf(acc3 * rd + b0v.w, 0.f)));
    float4 o1 = make_float4(rna_tf32(fmaxf(acc4 * rd + b1v.x, 0.f)),
                            rna_tf32(fmaxf(acc5 * rd + b1v.y, 0.f)),
                            rna_tf32(fmaxf(acc6 * rd + b1v.z, 0.f)),
                            rna_tf32(fmaxf(acc7 * rd + b1v.w, 0.f)));
    float* hp = h + (size_t)t * 256 + base;
    *(float4*)hp = o0;
    *(float4*)(hp + 4) = o1;
}

// ===========================================================================
// CSR gather (64-wide): dst[t] += sum_{s in CSR(t)} p[s]; optional relu.
// ===========================================================================
__global__ void gather_csr64_kernel(const float* __restrict__ p,
                                    const int* __restrict__ rowptr, const int* __restrict__ colidx,
                                    float* __restrict__ dst, int ldd, int relu) {
    int warp = (blockIdx.x * blockDim.x + threadIdx.x) >> 5;
    int lane = threadIdx.x & 31;
    if (warp >= NN) return;
    int t = warp;
    float* dp = dst + (size_t)t * ldd + lane * 2;
    float2 acc = *(float2*)dp;
    int beg = rowptr[t], end = rowptr[t + 1];
    for (int j = beg; j < end; j++) {
        int s = colidx[j];
        float2 v = *(const float2*)(p + (size_t)s * 64 + lane * 2);
        acc.x += v.x; acc.y += v.y;
    }
    if (relu) { acc.x = fmaxf(acc.x, 0.f); acc.y = fmaxf(acc.y, 0.f); }
    *(float2*)dp = acc;
}

// ===========================================================================
// Dual small GEMM (SIMT, K=64 layer): C1 = A@B1; C2 = A@B2 + bias
// ===========================================================================
__global__ void __launch_bounds__(256)
gemm64_dual_kernel(const float* __restrict__ A,
                   const float* __restrict__ B1, const float* __restrict__ B2,
                   const float* __restrict__ bias,
                   float* __restrict__ C1, float* __restrict__ C2,
                   int ldc2, int M, int K) {
    __shared__ float As[32][68];
    __shared__ float B1s[32][64];
    __shared__ float B2s[32][64];
    int m0 = blockIdx.x * 64;
    int tid = threadIdx.x;
    int tx = tid & 15, ty = tid >> 4;
    float acc1[4][4], acc2[4][4];
#pragma unroll
    for (int i = 0; i < 4; i++)
#pragma unroll
        for (int j = 0; j < 4; j++) { acc1[i][j] = 0.f; acc2[i][j] = 0.f; }

    for (int k0 = 0; k0 < K; k0 += 32) {
#pragma unroll
        for (int l = 0; l < 2; l++) {
            int lin = tid + l * 256;
            int row = lin >> 3, kc = (lin & 7) * 4;
            float4 v = make_float4(0.f, 0.f, 0.f, 0.f);
            int gm = m0 + row;
            if (gm < M) v = *(const float4*)(A + (size_t)gm * K + k0 + kc);
            As[kc + 0][row] = v.x; As[kc + 1][row] = v.y;
            As[kc + 2][row] = v.z; As[kc + 3][row] = v.w;

            int br = lin >> 4, bc = (lin & 15) * 4;
            *(float4*)&B1s[br][bc] = *(const float4*)(B1 + (size_t)(k0 + br) * 64 + bc);
            *(float4*)&B2s[br][bc] = *(const float4*)(B2 + (size_t)(k0 + br) * 64 + bc);
        }
        __syncthreads();
#pragma unroll
        for (int k = 0; k < 32; k++) {
            float a[4], b1v[4], b2v[4];
#pragma unroll
            for (int i = 0; i < 4; i++) a[i] = As[k][ty * 4 + i];
#pragma unroll
            for (int j = 0; j < 4; j++) { b1v[j] = B1s[k][tx * 4 + j]; b2v[j] = B2s[k][tx * 4 + j]; }
#pragma unroll
            for (int i = 0; i < 4; i++)
#pragma unroll
                for (int j = 0; j < 4; j++) {
                    acc1[i][j] += a[i] * b1v[j];
                    acc2[i][j] += a[i] * b2v[j];
                }
        }
        __syncthreads();
    }

    float bj[4];
#pragma unroll
    for (int j = 0; j < 4; j++) bj[j] = bias[tx * 4 + j];
#pragma unroll
    for (int i = 0; i < 4; i++) {
        int gm = m0 + ty * 4 + i;
        if (gm < M) {
            *(float4*)(C1 + (size_t)gm * 64 + tx * 4) =
                make_float4(acc1[i][0], acc1[i][1], acc1[i][2], acc1[i][3]);
            *(float4*)(C2 + (size_t)gm * ldc2 + tx * 4) =
                make_float4(acc2[i][0] + bj[0], acc2[i][1] + bj[1],
                            acc2[i][2] + bj[2], acc2[i][3] + bj[3]);
        }
    }
}

// ===========================================================================
// Host launch
// ===========================================================================
extern "C" void kernel_launch(void* const* d_in, const int* in_sizes, int n_in,
                              void* d_out, int out_size) {
    const float* x      = (const float*)d_in[0];
    const int*   ei     = (const int*)  d_in[1];   // [R,2,E]
    const float* Wl     = (const float*)d_in[2];   // [R,768,256]
    const float* Wr     = (const float*)d_in[3];
    const float* att    = (const float*)d_in[4];   // [R,4,64]
    const float* bg     = (const float*)d_in[5];   // [R,256]
    const float* Wrel1  = (const float*)d_in[6];   // [R,256,64]
    const float* Wroot1 = (const float*)d_in[7];
    const float* b1     = (const float*)d_in[8];   // [R,64]
    const float* Wrel2  = (const float*)d_in[9];   // [R,64,64]
    const float* Wroot2 = (const float*)d_in[10];
    const float* b2     = (const float*)d_in[11];  // [R,64]
    float* out = (float*)d_out;                    // [N,R,64]

    float* scratch = nullptr;
    cudaGetSymbolAddress((void**)&scratch, g_scratch);
    float* XLRbuf[2] = { scratch + OFF_XLR0, scratch + OFF_XLR1 };
    float* h   = scratch + OFF_H;
    float* h1  = scratch + OFF_H1;
    float* p1  = scratch + OFF_P1;
    float* p2  = scratch + OFF_P2;
    float* XR  = scratch + OFF_XR;
    float* WT  = scratch + OFF_WT;
    float* WB1 = scratch + OFF_WB1;

    int *rowptr = nullptr, *colidx = nullptr, *tmp = nullptr;
    cudaGetSymbolAddress((void**)&rowptr, g_rowptr);
    cudaGetSymbolAddress((void**)&colidx, g_colidx);
    cudaGetSymbolAddress((void**)&tmp, g_tmp);
    int* counts = tmp;
    int* cursor = tmp + RN * NN;

    // One-time host-side resources.
    static cudaStream_t sG = nullptr;
    static cudaEvent_t evPre, evG[RN], evFree[RN];
    if (!sG) {
        cudaStreamCreateWithFlags(&sG, cudaStreamNonBlocking);
        cudaEventCreateWithFlags(&evPre, cudaEventDisableTiming);
        for (int r = 0; r < RN; r++) {
            cudaEventCreateWithFlags(&evG[r], cudaEventDisableTiming);
            cudaEventCreateWithFlags(&evFree[r], cudaEventDisableTiming);
        }
        cudaFuncSetAttribute(gemm_mma_kernel<24, false>,
                             cudaFuncAttributeMaxDynamicSharedMemorySize, SMEM_GEMM);
        cudaFuncSetAttribute(gemm_mma_kernel<8, true>,
                             cudaFuncAttributeMaxDynamicSharedMemorySize, SMEM_GEMM);
    }

    const int M = NN;
    int nodeBlocks = (NN * 32 + 255) / 256;   // warp per node
    cudaStream_t sM = 0;  // main (capture-origin) stream

    // --- preprocessing (main stream) ---
    round_tf32_kernel<<<4096, 256, 0, sM>>>((const float4*)x, (float4*)XR, NN * DD / 4);
    transpose_w_kernel<<<dim3(24, 16, RN), dim3(32, 8), 0, sM>>>(Wl, Wr, WT);
    transpose_wb1_kernel<<<dim3(8, 4, RN), dim3(32, 8), 0, sM>>>(Wrel1, Wroot1, WB1);
    // CSR build (all relations)
    zero_int_kernel<<<1024, 256, 0, sM>>>(tmp, 2 * RN * NN);
    hist_kernel<<<(RN * EE + 255) / 256, 256, 0, sM>>>(ei, counts);
    scan_kernel<<<RN, 1024, 0, sM>>>(counts, rowptr);
    fillcsr_kernel<<<(RN * EE + 255) / 256, 256, 0, sM>>>(ei, rowptr, cursor, colidx);

    cudaEventRecord(evPre, sM);
    cudaStreamWaitEvent(sG, evPre, 0);

    for (int r = 0; r < RN; r++) {
        const int* rp = rowptr + r * (NN + 1);
        const int* ci = colidx + r * EE;
        float* XLR = XLRbuf[r & 1];

        // --- side stream: big GEMM for relation r ---
        if (r >= 2) cudaStreamWaitEvent(sG, evFree[r - 2], 0);
        gemm_mma_kernel<24, false><<<dim3(4, (M + BM - 1) / BM), 256, SMEM_GEMM, sG>>>(
            XR, WT + (size_t)r * 512 * DD, XLR, nullptr, nullptr, 512, M, DD);
        cudaEventRecord(evG[r], sG);

        // --- main stream: relation r pipeline ---
        cudaStreamWaitEvent(sM, evG[r], 0);

        // GATv2: CSR gather, fully fused (normalize + bias + relu + tf32 round)
        gat_csr_kernel<<<nodeBlocks, 256, 0, sM>>>(XLR, rp, ci,
                                                   att + (size_t)r * HC,
                                                   bg + (size_t)r * HC, h);
        cudaEventRecord(evFree[r], sM);  // last reader of XLRbuf[r&1]

        // GraphConv 1 (tensor path): p1 = h@Wrel1, h1 = h@Wroot1 + b1
        gemm_mma_kernel<8, true><<<dim3(1, (M + BM - 1) / BM), 256, SMEM_GEMM, sM>>>(
            h, WB1 + (size_t)r * 128 * HC, p1, h1, b1 + (size_t)r * OO, 64, M, HC);
        gather_csr64_kernel<<<nodeBlocks, 256, 0, sM>>>(p1, rp, ci, h1, OO, 1);

        // GraphConv 2 (SIMT, K=64) -> out[:, r, :]
        gemm64_dual_kernel<<<(M + 63) / 64, 256, 0, sM>>>(
            h1, Wrel2 + (size_t)r * OO * OO, Wroot2 + (size_t)r * OO * OO,
            b2 + (size_t)r * OO, p2, out + (size_t)r * OO, RN * OO, M, OO);
        gather_csr64_kernel<<<nodeBlocks, 256, 0, sM>>>(p2, rp, ci,
                                                        out + (size_t)r * OO, RN * OO, 0);
    }
}

// round 8
// speedup vs baseline: 3.6151x; 1.0598x over previous
#include <cuda_runtime.h>
#include <cstdint>
#include <cstddef>

// Problem constants (fixed by the reference)
#define RN 6
#define NN 50000
#define EE 200000
#define DD 768
#define HC 256      // H*C
#define OO 64

// ---------------------------------------------------------------------------
// Scratch layout (floats) — intermediates duplicated per relation parity
// ---------------------------------------------------------------------------
__device__ float g_scratch[136955904];

#define OFF_XLR0  0u
#define OFF_XLR1  25600000u
#define OFF_H0    51200000u
#define OFF_H1P   64000000u     // H parity 1
#define OFF_H1_0  76800000u
#define OFF_H1_1  80000000u
#define OFF_P1_0  83200000u
#define OFF_P1_1  86400000u
#define OFF_P2_0  89600000u
#define OFF_P2_1  92800000u
#define OFF_XR    96000000u
#define OFF_WT    134400000u
#define OFF_WB1   136759296u

// CSR structures (ints)
__device__ int g_rowptr[RN * (NN + 1)];
__device__ int g_colidx[RN * EE];
__device__ int g_tmp[2 * RN * NN];   // counts | cursor

// ===========================================================================
// PTX helpers (plain-sm_103-legal: cp.async, ldmatrix, mma.sync)
// ===========================================================================
__device__ __forceinline__ uint32_t smem_u32(const void* p) {
    uint32_t a;
    asm("{ .reg .u64 t; cvta.to.shared.u64 t, %1; cvt.u32.u64 %0, t; }"
        : "=r"(a) : "l"(p));
    return a;
}
__device__ __forceinline__ void cp16(uint32_t dst, const void* src, uint32_t sz) {
    asm volatile("cp.async.cg.shared.global [%0], [%1], 16, %2;"
                 :: "r"(dst), "l"(src), "r"(sz) : "memory");
}
__device__ __forceinline__ void cp_commit() {
    asm volatile("cp.async.commit_group;" ::: "memory");
}
__device__ __forceinline__ void cp_wait2() {
    asm volatile("cp.async.wait_group 2;" ::: "memory");
}
#define LDSM4(r0, r1, r2, r3, addr) \
    asm volatile("ldmatrix.sync.aligned.m8n8.x4.shared.b16 {%0,%1,%2,%3}, [%4];" \
                 : "=r"(r0), "=r"(r1), "=r"(r2), "=r"(r3) : "r"(addr))

#define MMA_TF32(d, a, b0, b1) \
    asm volatile("mma.sync.aligned.m16n8k8.row.col.f32.tf32.tf32.f32 " \
                 "{%0,%1,%2,%3}, {%4,%5,%6,%7}, {%8,%9}, {%0,%1,%2,%3};" \
                 : "+f"((d)[0]), "+f"((d)[1]), "+f"((d)[2]), "+f"((d)[3]) \
                 : "r"((a)[0]), "r"((a)[1]), "r"((a)[2]), "r"((a)[3]), \
                   "r"(b0), "r"(b1))

// ===========================================================================
// Preprocessing: tf32 rounding + weight transposes
// ===========================================================================
__device__ __forceinline__ float rna_tf32(float v) {
    uint32_t o;
    asm("cvt.rna.tf32.f32 %0, %1;" : "=r"(o) : "f"(v));
    return __uint_as_float(o);
}

__global__ void round_tf32_kernel(const float4* __restrict__ in, float4* __restrict__ out, int n4) {
    int i = blockIdx.x * blockDim.x + threadIdx.x;
    int stride = gridDim.x * blockDim.x;
    for (; i < n4; i += stride) {
        float4 v = in[i];
        v.x = rna_tf32(v.x); v.y = rna_tf32(v.y);
        v.z = rna_tf32(v.z); v.w = rna_tf32(v.w);
        out[i] = v;
    }
}

// WT[r][n][k] = rna(Wl[r][k][n]) for n<256 else rna(Wr[r][k][n-256])
__global__ void transpose_w_kernel(const float* __restrict__ Wl, const float* __restrict__ Wr,
                                   float* __restrict__ WT) {
    __shared__ float tile[32][33];
    int r = blockIdx.z;
    int k0 = blockIdx.x * 32;
    int n0 = blockIdx.y * 32;
    const float* W = (n0 < 256) ? Wl : Wr;
    int nc0 = (n0 < 256) ? n0 : (n0 - 256);
    int tx = threadIdx.x, ty = threadIdx.y;  // 32 x 8
#pragma unroll
    for (int i = 0; i < 32; i += 8) {
        float v = W[((size_t)r * DD + k0 + ty + i) * HC + nc0 + tx];
        tile[ty + i][tx] = rna_tf32(v);
    }
    __syncthreads();
#pragma unroll
    for (int i = 0; i < 32; i += 8) {
        WT[((size_t)r * 512 + n0 + ty + i) * DD + k0 + tx] = tile[tx][ty + i];
    }
}

// WB1[r][n][k] = rna(Wrel1[r][k][n]) for n<64 else rna(Wroot1[r][k][n-64]); K=256
__global__ void transpose_wb1_kernel(const float* __restrict__ Wrel1,
                                     const float* __restrict__ Wroot1,
                                     float* __restrict__ WB1) {
    __shared__ float tile[32][33];
    int r = blockIdx.z;
    int k0 = blockIdx.x * 32;   // 8 blocks (K=256)
    int n0 = blockIdx.y * 32;   // 4 blocks (N=128)
    const float* W = (n0 < 64) ? Wrel1 : Wroot1;
    int nc0 = (n0 < 64) ? n0 : (n0 - 64);
    int tx = threadIdx.x, ty = threadIdx.y;  // 32 x 8
#pragma unroll
    for (int i = 0; i < 32; i += 8) {
        float v = W[((size_t)r * HC + k0 + ty + i) * OO + nc0 + tx];
        tile[ty + i][tx] = rna_tf32(v);
    }
    __syncthreads();
#pragma unroll
    for (int i = 0; i < 32; i += 8) {
        WB1[((size_t)r * 128 + n0 + ty + i) * HC + k0 + tx] = tile[tx][ty + i];
    }
}

// ===========================================================================
// CSR build: zero -> histogram -> scan -> fill
// ===========================================================================
__global__ void zero_int_kernel(int* p, int n) {
    int i = blockIdx.x * blockDim.x + threadIdx.x;
    int stride = gridDim.x * blockDim.x;
    for (; i < n; i += stride) p[i] = 0;
}

__global__ void hist_kernel(const int* __restrict__ ei, int* __restrict__ counts) {
    int i = blockIdx.x * blockDim.x + threadIdx.x;
    if (i >= RN * EE) return;
    int r = i / EE, e = i - r * EE;
    int t = ei[(size_t)r * 2 * EE + EE + e];
    atomicAdd(&counts[r * NN + t], 1);
}

__global__ void __launch_bounds__(1024)
scan_kernel(const int* __restrict__ counts, int* __restrict__ rowptr) {
    int r = blockIdx.x;
    const int* c = counts + r * NN;
    int* rp = rowptr + r * (NN + 1);
    __shared__ int sdata[1024];
    __shared__ int carry_s;
    if (threadIdx.x == 0) { carry_s = 0; rp[0] = 0; }
    __syncthreads();
    for (int base = 0; base < NN; base += 1024) {
        int i = base + threadIdx.x;
        int v = (i < NN) ? c[i] : 0;
        sdata[threadIdx.x] = v;
        __syncthreads();
#pragma unroll
        for (int off = 1; off < 1024; off <<= 1) {
            int tv = (threadIdx.x >= off) ? sdata[threadIdx.x - off] : 0;
            __syncthreads();
            sdata[threadIdx.x] += tv;
            __syncthreads();
        }
        int carry = carry_s;
        if (i < NN) rp[i + 1] = carry + sdata[threadIdx.x];
        __syncthreads();
        if (threadIdx.x == 1023) carry_s = carry + sdata[1023];
        __syncthreads();
    }
}

__global__ void fillcsr_kernel(const int* __restrict__ ei, const int* __restrict__ rowptr,
                               int* __restrict__ cursor, int* __restrict__ colidx) {
    int i = blockIdx.x * blockDim.x + threadIdx.x;
    if (i >= RN * EE) return;
    int r = i / EE, e = i - r * EE;
    int s = ei[(size_t)r * 2 * EE + e];
    int t = ei[(size_t)r * 2 * EE + EE + e];
    int pos = rowptr[r * (NN + 1) + t] + atomicAdd(&cursor[r * NN + t], 1);
    colidx[r * EE + pos] = s;
}

// ===========================================================================
// Templated tf32 mma.sync GEMM (BM=128 BN=128 BK=32, 4-stage cp.async,
// 8 warps, warp tile 64x32, ks-double-buffered ldmatrix fragments).
//   non-DUAL: C[M][ldc] tile = A@B^T
//   DUAL: N=128, cols 0..63 -> C (ldc 64), cols 64..127 -> C2 + bias
// ===========================================================================
#define BM 128
#define BN 128
#define BK 32
#define GSTG 4
#define TILE_BYTES (BM * BK * 4)    // 16384
#define SMEM_GEMM (GSTG * 2 * TILE_BYTES + 1024)

template<int KITN, bool DUAL>
__global__ void __launch_bounds__(256, 1)
gemm_mma_kernel(const float* __restrict__ A, const float* __restrict__ B,
                float* __restrict__ C, float* __restrict__ C2,
                const float* __restrict__ bias, int ldc, int M, int K) {
    extern __shared__ char sm_raw[];
    uint32_t smbase = (smem_u32(sm_raw) + 1023u) & ~1023u;
    uint32_t sA = smbase;
    uint32_t sB = smbase + GSTG * TILE_BYTES;

    int tid = threadIdx.x;
    int lane = tid & 31, wid = tid >> 5;
    int wm = wid & 1, wn = wid >> 1;
    int M0 = blockIdx.y * BM, N0 = blockIdx.x * BN;

    uint32_t dstOff[4];
    const float* srcA[4]; uint32_t szA[4];
    const float* srcB[4];
#pragma unroll
    for (int i = 0; i < 4; i++) {
        int lin = tid + i * 256;
        int row = lin >> 3, ch = lin & 7;
        dstOff[i] = row * 128 + ((ch * 16) ^ ((row & 7) * 16));
        int ga = M0 + row;
        szA[i] = (ga < M) ? 16u : 0u;
        srcA[i] = A + (size_t)(ga < M ? ga : 0) * K + ch * 4;
        srcB[i] = B + (size_t)(N0 + row) * K + ch * 4;
    }

    uint32_t aOff[4], bOff[2];
#pragma unroll
    for (int mt = 0; mt < 4; mt++) {
        int rowA = wm * 64 + mt * 16 + (lane & 7) + ((lane >> 3) & 1) * 8;
        uint32_t q = (uint32_t)(((lane >> 4) * 16) ^ ((rowA & 7) * 16));
        aOff[mt] = (uint32_t)rowA * 128 + q;
    }
#pragma unroll
    for (int bp = 0; bp < 2; bp++) {
        int rowB = wn * 32 + bp * 16 + (lane & 7) + ((lane >> 4) & 1) * 8;
        uint32_t q = (uint32_t)((((lane >> 3) & 1) * 16) ^ ((rowB & 7) * 16));
        bOff[bp] = (uint32_t)rowB * 128 + q;
    }

    float acc[4][4][4];
#pragma unroll
    for (int mt = 0; mt < 4; mt++)
#pragma unroll
        for (int nt = 0; nt < 4; nt++)
#pragma unroll
            for (int j = 0; j < 4; j++) acc[mt][nt][j] = 0.f;

#pragma unroll
    for (int s = 0; s < 3; s++) {
#pragma unroll
        for (int i = 0; i < 4; i++) {
            cp16(sA + s * TILE_BYTES + dstOff[i], srcA[i] + s * BK, szA[i]);
            cp16(sB + s * TILE_BYTES + dstOff[i], srcB[i] + s * BK, 16u);
        }
        cp_commit();
    }

    uint32_t afr[2][4][4];
    uint32_t bfr[2][4][2];

    for (int it = 0; it < KITN; it++) {
        cp_wait2();
        __syncthreads();

        int nx = it + 3;
        if (nx < KITN) {
            int s2 = nx % GSTG;
#pragma unroll
            for (int i = 0; i < 4; i++) {
                cp16(sA + s2 * TILE_BYTES + dstOff[i], srcA[i] + nx * BK, szA[i]);
                cp16(sB + s2 * TILE_BYTES + dstOff[i], srcB[i] + nx * BK, 16u);
            }
        }
        cp_commit();

        int s = it % GSTG;
        uint32_t baseA = sA + s * TILE_BYTES;
        uint32_t baseB = sB + s * TILE_BYTES;

#pragma unroll
        for (int mt = 0; mt < 4; mt++)
            LDSM4(afr[0][mt][0], afr[0][mt][1], afr[0][mt][2], afr[0][mt][3],
                  baseA + aOff[mt]);
#pragma unroll
        for (int bp = 0; bp < 2; bp++) {
            uint32_t r0, r1, r2, r3;
            LDSM4(r0, r1, r2, r3, baseB + bOff[bp]);
            bfr[0][2 * bp][0] = r0;     bfr[0][2 * bp][1] = r1;
            bfr[0][2 * bp + 1][0] = r2; bfr[0][2 * bp + 1][1] = r3;
        }

#pragma unroll
        for (int ks = 0; ks < 4; ks++) {
            int cur = ks & 1;
            if (ks < 3) {
                int nb = cur ^ 1;
                uint32_t x = (uint32_t)((ks + 1) * 32);
#pragma unroll
                for (int mt = 0; mt < 4; mt++)
                    LDSM4(afr[nb][mt][0], afr[nb][mt][1], afr[nb][mt][2], afr[nb][mt][3],
                          baseA + (aOff[mt] ^ x));
#pragma unroll
                for (int bp = 0; bp < 2; bp++) {
                    uint32_t r0, r1, r2, r3;
                    LDSM4(r0, r1, r2, r3, baseB + (bOff[bp] ^ x));
                    bfr[nb][2 * bp][0] = r0;     bfr[nb][2 * bp][1] = r1;
                    bfr[nb][2 * bp + 1][0] = r2; bfr[nb][2 * bp + 1][1] = r3;
                }
            }
#pragma unroll
            for (int mt = 0; mt < 4; mt++)
#pragma unroll
                for (int nt = 0; nt < 4; nt++)
                    MMA_TF32(acc[mt][nt], afr[cur][mt], bfr[cur][nt][0], bfr[cur][nt][1]);
        }
    }

    int r = lane >> 2, c = (lane & 3) * 2;
#pragma unroll
    for (int mt = 0; mt < 4; mt++) {
        int grow = M0 + wm * 64 + mt * 16 + r;
#pragma unroll
        for (int nt = 0; nt < 4; nt++) {
            int gcol = wn * 32 + nt * 8 + c;
            float2 v01 = make_float2(acc[mt][nt][0], acc[mt][nt][1]);
            float2 v23 = make_float2(acc[mt][nt][2], acc[mt][nt][3]);
            if (DUAL) {
                if (gcol < 64) {
                    if (grow < M)     *(float2*)(C + (size_t)grow * 64 + gcol) = v01;
                    if (grow + 8 < M) *(float2*)(C + (size_t)(grow + 8) * 64 + gcol) = v23;
                } else {
                    float bx = bias[gcol - 64], by = bias[gcol - 63];
                    v01.x += bx; v01.y += by;
                    v23.x += bx; v23.y += by;
                    if (grow < M)     *(float2*)(C2 + (size_t)grow * 64 + gcol - 64) = v01;
                    if (grow + 8 < M) *(float2*)(C2 + (size_t)(grow + 8) * 64 + gcol - 64) = v23;
                }
            } else {
                if (grow < M)
                    *(float2*)(C + (size_t)grow * ldc + N0 + gcol) = v01;
                if (grow + 8 < M)
                    *(float2*)(C + (size_t)(grow + 8) * ldc + N0 + gcol) = v23;
            }
        }
    }
}

// ===========================================================================
// GATv2 CSR pass: warp per target node, software-pipelined edge loads.
// h[t] = relu(acc/denom + bias), tf32-rounded for the tensor GraphConv-1.
// ===========================================================================
__global__ void gat_csr_kernel(const float* __restrict__ XLR,
                               const int* __restrict__ rowptr, const int* __restrict__ colidx,
                               const float* __restrict__ att, const float* __restrict__ bias,
                               float* __restrict__ h) {
    int warp = (blockIdx.x * blockDim.x + threadIdx.x) >> 5;
    int lane = threadIdx.x & 31;
    if (warp >= NN) return;
    int t = warp;
    int base = lane * 8;

    float4 a0 = *(const float4*)(att + base), a1 = *(const float4*)(att + base + 4);
    const float* xrp = XLR + (size_t)t * 512 + 256 + base;
    float4 r0 = *(const float4*)xrp, r1 = *(const float4*)(xrp + 4);

    float acc0 = 0.f, acc1 = 0.f, acc2 = 0.f, acc3 = 0.f;
    float acc4 = 0.f, acc5 = 0.f, acc6 = 0.f, acc7 = 0.f;
    float denom = 0.f;

    int beg = rowptr[t], end = rowptr[t + 1];
    int deg = end - beg;

    // prologue: load item 0 (edge 0 or self-loop)
    int s0 = (deg > 0) ? colidx[beg] : t;
    const float* xp = XLR + (size_t)s0 * 512 + base;
    float4 l0 = *(const float4*)xp, l1 = *(const float4*)(xp + 4);

    for (int k = 0; k <= deg; k++) {
        float4 c0 = l0, c1 = l1;
        if (k < deg) {   // prefetch item k+1 (edge or self-loop) before compute
            int sn = (k + 1 < deg) ? colidx[beg + k + 1] : t;
            const float* np = XLR + (size_t)sn * 512 + base;
            l0 = *(const float4*)np;
            l1 = *(const float4*)(np + 4);
        }
#define LRELU(v) ((v) > 0.f ? (v) : 0.2f * (v))
        float sum = LRELU(c0.x + r0.x) * a0.x + LRELU(c0.y + r0.y) * a0.y
                  + LRELU(c0.z + r0.z) * a0.z + LRELU(c0.w + r0.w) * a0.w
                  + LRELU(c1.x + r1.x) * a1.x + LRELU(c1.y + r1.y) * a1.y
                  + LRELU(c1.z + r1.z) * a1.z + LRELU(c1.w + r1.w) * a1.w;
#undef LRELU
        sum += __shfl_xor_sync(0xffffffffu, sum, 1);
        sum += __shfl_xor_sync(0xffffffffu, sum, 2);
        sum += __shfl_xor_sync(0xffffffffu, sum, 4);
        float e = expf(sum);
        acc0 += e * c0.x; acc1 += e * c0.y; acc2 += e * c0.z; acc3 += e * c0.w;
        acc4 += e * c1.x; acc5 += e * c1.y; acc6 += e * c1.z; acc7 += e * c1.w;
        denom += e;
    }

    float rd = __frcp_rn(denom + 1e-16f);
    float4 b0v = *(const float4*)(bias + base), b1v = *(const float4*)(bias + base + 4);
    float4 o0 = make_float4(rna_tf32(fmaxf(acc0 * rd + b0v.x, 0.f)),
                            rna_tf32(fmaxf(acc1 * rd + b0v.y, 0.f)),
                            rna_tf32(fmaxf(acc2 * rd + b0v.z, 0.f)),
                            rna_tf32(fmaxf(acc3 * rd + b0v.w, 0.f)));
    float4 o1 = make_float4(rna_tf32(fmaxf(acc4 * rd + b1v.x, 0.f)),
                            rna_tf32(fmaxf(acc5 * rd + b1v.y, 0.f)),
                            rna_tf32(fmaxf(acc6 * rd + b1v.z, 0.f)),
                            rna_tf32(fmaxf(acc7 * rd + b1v.w, 0.f)));
    float* hp = h + (size_t)t * 256 + base;
    *(float4*)hp = o0;
    *(float4*)(hp + 4) = o1;
}

// ===========================================================================
// CSR gather (64-wide), software-pipelined: dst[t] += sum p[s]; optional relu
// ===========================================================================
__global__ void gather_csr64_kernel(const float* __restrict__ p,
                                    const int* __restrict__ rowptr, const int* __restrict__ colidx,
                                    float* __restrict__ dst, int ldd, int relu) {
    int warp = (blockIdx.x * blockDim.x + threadIdx.x) >> 5;
    int lane = threadIdx.x & 31;
    if (warp >= NN) return;
    int t = warp;
    float* dp = dst + (size_t)t * ldd + lane * 2;
    float2 acc = *(float2*)dp;
    int beg = rowptr[t], end = rowptr[t + 1];
    if (beg < end) {
        int s = colidx[beg];
        float2 v = *(const float2*)(p + (size_t)s * 64 + lane * 2);
        for (int j = beg + 1; j < end; j++) {
            int s2 = colidx[j];
            float2 v2 = *(const float2*)(p + (size_t)s2 * 64 + lane * 2);
            acc.x += v.x; acc.y += v.y;
            v = v2;
        }
        acc.x += v.x; acc.y += v.y;
    }
    if (relu) { acc.x = fmaxf(acc.x, 0.f); acc.y = fmaxf(acc.y, 0.f); }
    *(float2*)dp = acc;
}

// ===========================================================================
// Dual small GEMM (SIMT, K=64 layer): C1 = A@B1; C2 = A@B2 + bias
// ===========================================================================
__global__ void __launch_bounds__(256)
gemm64_dual_kernel(const float* __restrict__ A,
                   const float* __restrict__ B1, const float* __restrict__ B2,
                   const float* __restrict__ bias,
                   float* __restrict__ C1, float* __restrict__ C2,
                   int ldc2, int M, int K) {
    __shared__ float As[32][68];
    __shared__ float B1s[32][64];
    __shared__ float B2s[32][64];
    int m0 = blockIdx.x * 64;
    int tid = threadIdx.x;
    int tx = tid & 15, ty = tid >> 4;
    float acc1[4][4], acc2[4][4];
#pragma unroll
    for (int i = 0; i < 4; i++)
#pragma unroll
        for (int j = 0; j < 4; j++) { acc1[i][j] = 0.f; acc2[i][j] = 0.f; }

    for (int k0 = 0; k0 < K; k0 += 32) {
#pragma unroll
        for (int l = 0; l < 2; l++) {
            int lin = tid + l * 256;
            int row = lin >> 3, kc = (lin & 7) * 4;
            float4 v = make_float4(0.f, 0.f, 0.f, 0.f);
            int gm = m0 + row;
            if (gm < M) v = *(const float4*)(A + (size_t)gm * K + k0 + kc);
            As[kc + 0][row] = v.x; As[kc + 1][row] = v.y;
            As[kc + 2][row] = v.z; As[kc + 3][row] = v.w;

            int br = lin >> 4, bc = (lin & 15) * 4;
            *(float4*)&B1s[br][bc] = *(const float4*)(B1 + (size_t)(k0 + br) * 64 + bc);
            *(float4*)&B2s[br][bc] = *(const float4*)(B2 + (size_t)(k0 + br) * 64 + bc);
        }
        __syncthreads();
#pragma unroll
        for (int k = 0; k < 32; k++) {
            float a[4], b1v[4], b2v[4];
#pragma unroll
            for (int i = 0; i < 4; i++) a[i] = As[k][ty * 4 + i];
#pragma unroll
            for (int j = 0; j < 4; j++) { b1v[j] = B1s[k][tx * 4 + j]; b2v[j] = B2s[k][tx * 4 + j]; }
#pragma unroll
            for (int i = 0; i < 4; i++)
#pragma unroll
                for (int j = 0; j < 4; j++) {
                    acc1[i][j] += a[i] * b1v[j];
                    acc2[i][j] += a[i] * b2v[j];
                }
        }
        __syncthreads();
    }

    float bj[4];
#pragma unroll
    for (int j = 0; j < 4; j++) bj[j] = bias[tx * 4 + j];
#pragma unroll
    for (int i = 0; i < 4; i++) {
        int gm = m0 + ty * 4 + i;
        if (gm < M) {
            *(float4*)(C1 + (size_t)gm * 64 + tx * 4) =
                make_float4(acc1[i][0], acc1[i][1], acc1[i][2], acc1[i][3]);
            *(float4*)(C2 + (size_t)gm * ldc2 + tx * 4) =
                make_float4(acc2[i][0] + bj[0], acc2[i][1] + bj[1],
                            acc2[i][2] + bj[2], acc2[i][3] + bj[3]);
        }
    }
}

// ===========================================================================
// Host launch: 3-stream fork-join — sG carries the GEMM spine; main chains
// alternate between stream 0 (parity 0) and sM2 (parity 1).
// ===========================================================================
extern "C" void kernel_launch(void* const* d_in, const int* in_sizes, int n_in,
                              void* d_out, int out_size) {
    const float* x      = (const float*)d_in[0];
    const int*   ei     = (const int*)  d_in[1];   // [R,2,E]
    const float* Wl     = (const float*)d_in[2];   // [R,768,256]
    const float* Wr     = (const float*)d_in[3];
    const float* att    = (const float*)d_in[4];   // [R,4,64]
    const float* bg     = (const float*)d_in[5];   // [R,256]
    const float* Wrel1  = (const float*)d_in[6];   // [R,256,64]
    const float* Wroot1 = (const float*)d_in[7];
    const float* b1     = (const float*)d_in[8];   // [R,64]
    const float* Wrel2  = (const float*)d_in[9];   // [R,64,64]
    const float* Wroot2 = (const float*)d_in[10];
    const float* b2     = (const float*)d_in[11];  // [R,64]
    float* out = (float*)d_out;                    // [N,R,64]

    float* scratch = nullptr;
    cudaGetSymbolAddress((void**)&scratch, g_scratch);
    float* XLRbuf[2] = { scratch + OFF_XLR0, scratch + OFF_XLR1 };
    float* Hb[2]  = { scratch + OFF_H0,   scratch + OFF_H1P };
    float* H1b[2] = { scratch + OFF_H1_0, scratch + OFF_H1_1 };
    float* P1b[2] = { scratch + OFF_P1_0, scratch + OFF_P1_1 };
    float* P2b[2] = { scratch + OFF_P2_0, scratch + OFF_P2_1 };
    float* XR  = scratch + OFF_XR;
    float* WT  = scratch + OFF_WT;
    float* WB1 = scratch + OFF_WB1;

    int *rowptr = nullptr, *colidx = nullptr, *tmp = nullptr;
    cudaGetSymbolAddress((void**)&rowptr, g_rowptr);
    cudaGetSymbolAddress((void**)&colidx, g_colidx);
    cudaGetSymbolAddress((void**)&tmp, g_tmp);
    int* counts = tmp;
    int* cursor = tmp + RN * NN;

    // One-time host-side resources.
    static cudaStream_t sG = nullptr, sM2 = nullptr;
    static cudaEvent_t evFork, evPre, evCSR, evEnd, evG[RN], evFree[RN];
    if (!sG) {
        cudaStreamCreateWithFlags(&sG, cudaStreamNonBlocking);
        cudaStreamCreateWithFlags(&sM2, cudaStreamNonBlocking);
        cudaEventCreateWithFlags(&evFork, cudaEventDisableTiming);
        cudaEventCreateWithFlags(&evPre, cudaEventDisableTiming);
        cudaEventCreateWithFlags(&evCSR, cudaEventDisableTiming);
        cudaEventCreateWithFlags(&evEnd, cudaEventDisableTiming);
        for (int r = 0; r < RN; r++) {
            cudaEventCreateWithFlags(&evG[r], cudaEventDisableTiming);
            cudaEventCreateWithFlags(&evFree[r], cudaEventDisableTiming);
        }
        cudaFuncSetAttribute(gemm_mma_kernel<24, false>,
                             cudaFuncAttributeMaxDynamicSharedMemorySize, SMEM_GEMM);
        cudaFuncSetAttribute(gemm_mma_kernel<8, true>,
                             cudaFuncAttributeMaxDynamicSharedMemorySize, SMEM_GEMM);
    }

    const int M = NN;
    int nodeBlocks = (NN * 32 + 255) / 256;   // warp per node
    cudaStream_t s0 = 0;  // capture-origin stream

    // --- preprocessing: rounding/transposes on s0; CSR build on sM2 ---
    round_tf32_kernel<<<4096, 256, 0, s0>>>((const float4*)x, (float4*)XR, NN * DD / 4);
    cudaEventRecord(evFork, s0);
    cudaStreamWaitEvent(sM2, evFork, 0);

    // sM2: CSR build
    zero_int_kernel<<<1024, 256, 0, sM2>>>(tmp, 2 * RN * NN);
    hist_kernel<<<(RN * EE + 255) / 256, 256, 0, sM2>>>(ei, counts);
    scan_kernel<<<RN, 1024, 0, sM2>>>(counts, rowptr);
    fillcsr_kernel<<<(RN * EE + 255) / 256, 256, 0, sM2>>>(ei, rowptr, cursor, colidx);
    cudaEventRecord(evCSR, sM2);

    // s0: weight transposes
    transpose_w_kernel<<<dim3(24, 16, RN), dim3(32, 8), 0, s0>>>(Wl, Wr, WT);
    transpose_wb1_kernel<<<dim3(8, 4, RN), dim3(32, 8), 0, s0>>>(Wrel1, Wroot1, WB1);
    cudaEventRecord(evPre, s0);

    cudaStreamWaitEvent(sG, evPre, 0);   // GEMMs need XR + WT
    cudaStreamWaitEvent(s0, evCSR, 0);   // parity-0 mains need CSR
    cudaStreamWaitEvent(sM2, evPre, 0);  // parity-1 mains need WB1

    for (int r = 0; r < RN; r++) {
        const int* rp = rowptr + r * (NN + 1);
        const int* ci = colidx + r * EE;
        int par = r & 1;
        float* XLR = XLRbuf[par];
        cudaStream_t sP = par ? sM2 : s0;

        // --- sG: big GEMM for relation r ---
        if (r >= 2) cudaStreamWaitEvent(sG, evFree[r - 2], 0);
        gemm_mma_kernel<24, false><<<dim3(4, (M + BM - 1) / BM), 256, SMEM_GEMM, sG>>>(
            XR, WT + (size_t)r * 512 * DD, XLR, nullptr, nullptr, 512, M, DD);
        cudaEventRecord(evG[r], sG);

        // --- main chain for relation r on its parity stream ---
        cudaStreamWaitEvent(sP, evG[r], 0);

        gat_csr_kernel<<<nodeBlocks, 256, 0, sP>>>(XLR, rp, ci,
                                                   att + (size_t)r * HC,
                                                   bg + (size_t)r * HC, Hb[par]);
        cudaEventRecord(evFree[r], sP);  // last reader of XLRbuf[par]

        // GraphConv 1 (tensor): P1 = h@Wrel1, H1 = h@Wroot1 + b1
        gemm_mma_kernel<8, true><<<dim3(1, (M + BM - 1) / BM), 256, SMEM_GEMM, sP>>>(
            Hb[par], WB1 + (size_t)r * 128 * HC, P1b[par], H1b[par],
            b1 + (size_t)r * OO, 64, M, HC);
        gather_csr64_kernel<<<nodeBlocks, 256, 0, sP>>>(P1b[par], rp, ci, H1b[par], OO, 1);

        // GraphConv 2 (SIMT, K=64) -> out[:, r, :]
        gemm64_dual_kernel<<<(M + 63) / 64, 256, 0, sP>>>(
            H1b[par], Wrel2 + (size_t)r * OO * OO, Wroot2 + (size_t)r * OO * OO,
            b2 + (size_t)r * OO, P2b[par], out + (size_t)r * OO, RN * OO, M, OO);
        gather_csr64_kernel<<<nodeBlocks, 256, 0, sP>>>(P2b[par], rp, ci,
                                                        out + (size_t)r * OO, RN * OO, 0);
    }

    // join parity-1 stream back into the capture-origin stream
    cudaEventRecord(evEnd, sM2);
    cudaStreamWaitEvent(s0, evEnd, 0);
}